// round 1
// baseline (speedup 1.0000x reference)
#include <cuda_runtime.h>
#include <cuda_bf16.h>
#include <math.h>

// Problem constants
#define Bq 2
#define Tq 2048
#define Dq 1024
#define Hq 16
#define DKq 64
#define Mq (Bq*Tq)   // 4096

// ---------------- scratch (device globals; no allocation allowed) ----------
__device__ float g_Q[Mq * Dq];
__device__ float g_K[Mq * Dq];
__device__ float g_V[Mq * Dq];
__device__ float g_C[Mq * Dq];

// ---------------- SGEMM: Y = X @ W + bias ----------------------------------
// X: (M,K) row-major, W: (K,N) row-major, bias: (N), Y: (M,N)
// BM=BN=128, BK=8, 256 threads, 8x8 micro-tile per thread.
#define BM 128
#define BN 128
#define BK 8

__global__ __launch_bounds__(256, 2)
void sgemm_bias_kernel(const float* __restrict__ X,
                       const float* __restrict__ W,
                       const float* __restrict__ bias,
                       float* __restrict__ Y,
                       int M, int N, int K)
{
    __shared__ float As[BK][BM];   // A stored transposed: As[k][m]
    __shared__ float Bs[BK][BN];

    const int tid = threadIdx.x;
    const int tx = tid & 15;       // 0..15  -> col group
    const int ty = tid >> 4;       // 0..15  -> row group

    const int bm = blockIdx.y;
    const int bn = blockIdx.x;

    // load mapping
    const int a_row = tid >> 1;          // 0..127
    const int a_col = (tid & 1) * 4;     // 0 or 4
    const int b_row = tid >> 5;          // 0..7
    const int b_col = (tid & 31) * 4;    // 0..124

    const float* Xp = X + (size_t)(bm * BM) * K;
    const float* Wp = W + bn * BN;

    float acc[8][8];
#pragma unroll
    for (int i = 0; i < 8; ++i)
#pragma unroll
        for (int j = 0; j < 8; ++j) acc[i][j] = 0.f;

    for (int k0 = 0; k0 < K; k0 += BK) {
        float4 av = *(const float4*)(Xp + (size_t)a_row * K + k0 + a_col);
        As[a_col + 0][a_row] = av.x;
        As[a_col + 1][a_row] = av.y;
        As[a_col + 2][a_row] = av.z;
        As[a_col + 3][a_row] = av.w;
        float4 bv = *(const float4*)(Wp + (size_t)(k0 + b_row) * N + b_col);
        *(float4*)&Bs[b_row][b_col] = bv;
        __syncthreads();

#pragma unroll
        for (int k = 0; k < BK; ++k) {
            float ra[8], rb[8];
            float4 a0 = *(const float4*)&As[k][ty * 8];
            float4 a1 = *(const float4*)&As[k][ty * 8 + 4];
            ra[0]=a0.x; ra[1]=a0.y; ra[2]=a0.z; ra[3]=a0.w;
            ra[4]=a1.x; ra[5]=a1.y; ra[6]=a1.z; ra[7]=a1.w;
            float4 b0 = *(const float4*)&Bs[k][tx * 8];
            float4 b1 = *(const float4*)&Bs[k][tx * 8 + 4];
            rb[0]=b0.x; rb[1]=b0.y; rb[2]=b0.z; rb[3]=b0.w;
            rb[4]=b1.x; rb[5]=b1.y; rb[6]=b1.z; rb[7]=b1.w;
#pragma unroll
            for (int i = 0; i < 8; ++i)
#pragma unroll
                for (int j = 0; j < 8; ++j)
                    acc[i][j] += ra[i] * rb[j];
        }
        __syncthreads();
    }

    // epilogue with bias
    const int row0 = bm * BM + ty * 8;
    const int col0 = bn * BN + tx * 8;
    float4 bia0 = *(const float4*)(bias + col0);
    float4 bia1 = *(const float4*)(bias + col0 + 4);
#pragma unroll
    for (int i = 0; i < 8; ++i) {
        float4 o0, o1;
        o0.x = acc[i][0] + bia0.x; o0.y = acc[i][1] + bia0.y;
        o0.z = acc[i][2] + bia0.z; o0.w = acc[i][3] + bia0.w;
        o1.x = acc[i][4] + bia1.x; o1.y = acc[i][5] + bia1.y;
        o1.z = acc[i][6] + bia1.z; o1.w = acc[i][7] + bia1.w;
        *(float4*)(Y + (size_t)(row0 + i) * N + col0)     = o0;
        *(float4*)(Y + (size_t)(row0 + i) * N + col0 + 4) = o1;
    }
}

// ---------------- Flash attention (fp32, causal) ----------------------------
// Grid: (T/64, H, B). 256 threads. 64x64 Q tile, 64x64 K/V tiles.
// Q,K,V layout: (B,T,D) with head h occupying columns [h*64, h*64+64).
#define QT 64
#define KT 64
#define LDS_PAD 65   // row stride (floats) to dodge bank conflicts

__global__ __launch_bounds__(256, 2)
void attn_kernel(const float* __restrict__ Q,
                 const float* __restrict__ K,
                 const float* __restrict__ V,
                 float* __restrict__ Ctx)
{
    extern __shared__ float sm[];
    float* Qt = sm;                       // [64][65]  Qt[d][r]
    float* Kt = Qt + 64 * LDS_PAD;        // [64][65]  Kt[d][c]
    float* Vs = Kt + 64 * LDS_PAD;        // [64][65]  Vs[k][d]
    float* Ss = Vs + 64 * LDS_PAD;        // [64][65]  scores / probs
    float* m_s  = Ss + 64 * LDS_PAD;      // [64]
    float* l_s  = m_s + 64;               // [64]
    float* al_s = l_s + 64;               // [64]

    const int b  = blockIdx.z;
    const int h  = blockIdx.y;
    const int qb = blockIdx.x;
    const int tid = threadIdx.x;
    const int tx = tid & 15;   // col group (0..15)
    const int ty = tid >> 4;   // row group (0..15)

    const float* Qg = Q + ((size_t)b * Tq + qb * QT) * Dq + h * DKq;

    // load Q transposed (d-major)
    for (int i = tid; i < 64 * 64; i += 256) {
        int r = i >> 6, d = i & 63;
        Qt[d * LDS_PAD + r] = Qg[(size_t)r * Dq + d];
    }
    if (tid < 64) { m_s[tid] = -INFINITY; l_s[tid] = 0.f; }

    float o[4][4];
#pragma unroll
    for (int i = 0; i < 4; ++i)
#pragma unroll
        for (int j = 0; j < 4; ++j) o[i][j] = 0.f;

    __syncthreads();

    const float scale = 0.125f;  // 1/sqrt(64)

    for (int kb = 0; kb <= qb; ++kb) {
        const float* Kg = K + ((size_t)b * Tq + kb * KT) * Dq + h * DKq;
        const float* Vg = V + ((size_t)b * Tq + kb * KT) * Dq + h * DKq;
        for (int i = tid; i < 64 * 64; i += 256) {
            int r = i >> 6, d = i & 63;
            float kv = Kg[(size_t)r * Dq + d];
            float vv = Vg[(size_t)r * Dq + d];
            Kt[d * LDS_PAD + r] = kv;   // transposed
            Vs[r * LDS_PAD + d] = vv;   // natural
        }
        __syncthreads();

        // S = Q @ K^T  (each thread: 4x4)
        float s[4][4];
#pragma unroll
        for (int i = 0; i < 4; ++i)
#pragma unroll
            for (int j = 0; j < 4; ++j) s[i][j] = 0.f;

#pragma unroll 8
        for (int d = 0; d < 64; ++d) {
            float qa[4], kv[4];
#pragma unroll
            for (int i = 0; i < 4; ++i) qa[i] = Qt[d * LDS_PAD + ty * 4 + i];
#pragma unroll
            for (int j = 0; j < 4; ++j) kv[j] = Kt[d * LDS_PAD + tx * 4 + j];
#pragma unroll
            for (int i = 0; i < 4; ++i)
#pragma unroll
                for (int j = 0; j < 4; ++j)
                    s[i][j] += qa[i] * kv[j];
        }

        const bool diag = (kb == qb);
#pragma unroll
        for (int i = 0; i < 4; ++i) {
            int qi = ty * 4 + i;
#pragma unroll
            for (int j = 0; j < 4; ++j) {
                int ki = tx * 4 + j;
                float v = s[i][j] * scale;
                if (diag && ki > qi) v = -INFINITY;
                Ss[qi * LDS_PAD + ki] = v;
            }
        }
        __syncthreads();

        // online softmax per row (threads 0..63)
        if (tid < 64) {
            const int r = tid;
            float mold = m_s[r];
            float mx = mold;
            for (int j = 0; j < 64; ++j) mx = fmaxf(mx, Ss[r * LDS_PAD + j]);
            float alpha = __expf(mold - mx);
            float sum = 0.f;
            for (int j = 0; j < 64; ++j) {
                float p = __expf(Ss[r * LDS_PAD + j] - mx);
                Ss[r * LDS_PAD + j] = p;
                sum += p;
            }
            m_s[r] = mx;
            l_s[r] = l_s[r] * alpha + sum;
            al_s[r] = alpha;
        }
        __syncthreads();

        // O = O*alpha + P @ V
        float a[4];
#pragma unroll
        for (int i = 0; i < 4; ++i) a[i] = al_s[ty * 4 + i];
#pragma unroll
        for (int i = 0; i < 4; ++i)
#pragma unroll
            for (int j = 0; j < 4; ++j) o[i][j] *= a[i];

#pragma unroll 8
        for (int k = 0; k < 64; ++k) {
            float p[4], vv[4];
#pragma unroll
            for (int i = 0; i < 4; ++i) p[i] = Ss[(ty * 4 + i) * LDS_PAD + k];
#pragma unroll
            for (int j = 0; j < 4; ++j) vv[j] = Vs[k * LDS_PAD + tx * 4 + j];
#pragma unroll
            for (int i = 0; i < 4; ++i)
#pragma unroll
                for (int j = 0; j < 4; ++j)
                    o[i][j] += p[i] * vv[j];
        }
        __syncthreads();
    }

    // write context (B,T,D) with head offset
    float* Cg = Ctx + ((size_t)b * Tq + qb * QT) * Dq + h * DKq;
#pragma unroll
    for (int i = 0; i < 4; ++i) {
        float inv = 1.f / l_s[ty * 4 + i];
#pragma unroll
        for (int j = 0; j < 4; ++j)
            Cg[(size_t)(ty * 4 + i) * Dq + tx * 4 + j] = o[i][j] * inv;
    }
}

// ---------------- launch ----------------------------------------------------
extern "C" void kernel_launch(void* const* d_in, const int* in_sizes, int n_in,
                              void* d_out, int out_size)
{
    const float* x  = (const float*)d_in[0];
    const float* Wq = (const float*)d_in[1];
    const float* bq = (const float*)d_in[2];
    const float* Wk = (const float*)d_in[3];
    const float* bk = (const float*)d_in[4];
    const float* Wv = (const float*)d_in[5];
    const float* bv = (const float*)d_in[6];
    const float* Wo = (const float*)d_in[7];
    const float* bo = (const float*)d_in[8];
    float* out = (float*)d_out;

    float *pQ, *pK, *pV, *pC;
    cudaGetSymbolAddress((void**)&pQ, g_Q);
    cudaGetSymbolAddress((void**)&pK, g_K);
    cudaGetSymbolAddress((void**)&pV, g_V);
    cudaGetSymbolAddress((void**)&pC, g_C);

    const int SMEM_ATTN = (4 * 64 * LDS_PAD + 3 * 64) * (int)sizeof(float);
    cudaFuncSetAttribute(attn_kernel,
                         cudaFuncAttributeMaxDynamicSharedMemorySize, SMEM_ATTN);

    dim3 gGemm(Dq / BN, Mq / BM);   // (8, 32)
    dim3 bGemm(256);

    // projections
    sgemm_bias_kernel<<<gGemm, bGemm>>>(x, Wq, bq, pQ, Mq, Dq, Dq);
    sgemm_bias_kernel<<<gGemm, bGemm>>>(x, Wk, bk, pK, Mq, Dq, Dq);
    sgemm_bias_kernel<<<gGemm, bGemm>>>(x, Wv, bv, pV, Mq, Dq, Dq);

    // attention
    dim3 gAttn(Tq / QT, Hq, Bq);    // (32, 16, 2)
    attn_kernel<<<gAttn, 256, SMEM_ATTN>>>(pQ, pK, pV, pC);

    // output projection
    sgemm_bias_kernel<<<gGemm, bGemm>>>(pC, Wo, bo, out, Mq, Dq, Dq);
}

// round 2
// speedup vs baseline: 1.0331x; 1.0331x over previous
#include <cuda_runtime.h>
#include <cuda_bf16.h>
#include <math.h>

// Problem constants
#define Bq 2
#define Tq 2048
#define Dq 1024
#define Hq 16
#define DKq 64
#define Mq (Bq*Tq)   // 4096

// ---------------- scratch (device globals; no allocation allowed) ----------
__device__ float g_Q[Mq * Dq];
__device__ float g_K[Mq * Dq];
__device__ float g_V[Mq * Dq];
__device__ float g_C[Mq * Dq];

// ---------------- SGEMM core: Y = X @ W + bias ------------------------------
// X: (M,K) row-major, W: (K,N) row-major, bias: (N), Y: (M,N)
// BM=BN=128, BK=8, 256 threads, 8x8 micro-tile per thread.
#define BM 128
#define BN 128
#define BK 8

__device__ __forceinline__
void sgemm_body(const float* __restrict__ X,
                const float* __restrict__ W,
                const float* __restrict__ bias,
                float* __restrict__ Y,
                int M, int N, int K,
                int bm, int bn)
{
    __shared__ float As[BK][BM];   // A stored transposed: As[k][m]
    __shared__ float Bs[BK][BN];

    const int tid = threadIdx.x;
    const int tx = tid & 15;       // 0..15  -> col group
    const int ty = tid >> 4;       // 0..15  -> row group

    // load mapping
    const int a_row = tid >> 1;          // 0..127
    const int a_col = (tid & 1) * 4;     // 0 or 4
    const int b_row = tid >> 5;          // 0..7
    const int b_col = (tid & 31) * 4;    // 0..124

    const float* Xp = X + (size_t)(bm * BM) * K;
    const float* Wp = W + bn * BN;

    float acc[8][8];
#pragma unroll
    for (int i = 0; i < 8; ++i)
#pragma unroll
        for (int j = 0; j < 8; ++j) acc[i][j] = 0.f;

    for (int k0 = 0; k0 < K; k0 += BK) {
        float4 av = *(const float4*)(Xp + (size_t)a_row * K + k0 + a_col);
        As[a_col + 0][a_row] = av.x;
        As[a_col + 1][a_row] = av.y;
        As[a_col + 2][a_row] = av.z;
        As[a_col + 3][a_row] = av.w;
        float4 bv = *(const float4*)(Wp + (size_t)(k0 + b_row) * N + b_col);
        *(float4*)&Bs[b_row][b_col] = bv;
        __syncthreads();

#pragma unroll
        for (int k = 0; k < BK; ++k) {
            float ra[8], rb[8];
            float4 a0 = *(const float4*)&As[k][ty * 8];
            float4 a1 = *(const float4*)&As[k][ty * 8 + 4];
            ra[0]=a0.x; ra[1]=a0.y; ra[2]=a0.z; ra[3]=a0.w;
            ra[4]=a1.x; ra[5]=a1.y; ra[6]=a1.z; ra[7]=a1.w;
            float4 b0 = *(const float4*)&Bs[k][tx * 8];
            float4 b1 = *(const float4*)&Bs[k][tx * 8 + 4];
            rb[0]=b0.x; rb[1]=b0.y; rb[2]=b0.z; rb[3]=b0.w;
            rb[4]=b1.x; rb[5]=b1.y; rb[6]=b1.z; rb[7]=b1.w;
#pragma unroll
            for (int i = 0; i < 8; ++i)
#pragma unroll
                for (int j = 0; j < 8; ++j)
                    acc[i][j] += ra[i] * rb[j];
        }
        __syncthreads();
    }

    const int row0 = bm * BM + ty * 8;
    const int col0 = bn * BN + tx * 8;
    float4 bia0 = *(const float4*)(bias + col0);
    float4 bia1 = *(const float4*)(bias + col0 + 4);
#pragma unroll
    for (int i = 0; i < 8; ++i) {
        float4 o0, o1;
        o0.x = acc[i][0] + bia0.x; o0.y = acc[i][1] + bia0.y;
        o0.z = acc[i][2] + bia0.z; o0.w = acc[i][3] + bia0.w;
        o1.x = acc[i][4] + bia1.x; o1.y = acc[i][5] + bia1.y;
        o1.z = acc[i][6] + bia1.z; o1.w = acc[i][7] + bia1.w;
        *(float4*)(Y + (size_t)(row0 + i) * N + col0)     = o0;
        *(float4*)(Y + (size_t)(row0 + i) * N + col0 + 4) = o1;
    }
}

__global__ __launch_bounds__(256, 2)
void sgemm_bias_kernel(const float* __restrict__ X,
                       const float* __restrict__ W,
                       const float* __restrict__ bias,
                       float* __restrict__ Y,
                       int M, int N, int K)
{
    sgemm_body(X, W, bias, Y, M, N, K, blockIdx.y, blockIdx.x);
}

// Fused Q/K/V projections: gridDim.z selects which projection.
__global__ __launch_bounds__(256, 2)
void sgemm_qkv_kernel(const float* __restrict__ X,
                      const float* __restrict__ Wq, const float* __restrict__ bqv,
                      const float* __restrict__ Wk, const float* __restrict__ bkv,
                      const float* __restrict__ Wv, const float* __restrict__ bvv,
                      float* __restrict__ Qo, float* __restrict__ Ko, float* __restrict__ Vo)
{
    const float* W; const float* bias; float* Y;
    if (blockIdx.z == 0)      { W = Wq; bias = bqv; Y = Qo; }
    else if (blockIdx.z == 1) { W = Wk; bias = bkv; Y = Ko; }
    else                      { W = Wv; bias = bvv; Y = Vo; }
    sgemm_body(X, W, bias, Y, Mq, Dq, Dq, blockIdx.y, blockIdx.x);
}

// ---------------- Flash attention (fp32, causal) ----------------------------
// Grid: (T/64, H, B). 256 threads. 64x64 Q tile, 64x64 K/V tiles.
// Register-resident online softmax with shfl row reductions.
#define QT 64
#define KT 64
#define PAD 68   // float4-aligned row stride; transposed stores are 4-way (pay once)

__global__ __launch_bounds__(256, 2)
void attn_kernel(const float* __restrict__ Q,
                 const float* __restrict__ K,
                 const float* __restrict__ V,
                 float* __restrict__ Ctx)
{
    extern __shared__ float sm[];
    float* Qt = sm;                // [64][PAD]  Qt[d][r], pre-scaled
    float* Kt = Qt + 64 * PAD;     // [64][PAD]  Kt[d][c]
    float* Vs = Kt + 64 * PAD;     // [64][PAD]  Vs[k][d]
    float* Ps = Vs + 64 * PAD;     // [64][PAD]  probs

    const int b  = blockIdx.z;
    const int h  = blockIdx.y;
    const int qb = blockIdx.x;
    const int tid = threadIdx.x;
    const int tx = tid & 15;   // col group (0..15)
    const int ty = tid >> 4;   // row group (0..15)

    const float* Qg = Q + ((size_t)b * Tq + qb * QT) * Dq + h * DKq;

    // load Q transposed (d-major), pre-scaled by 1/sqrt(dk)
    for (int i = tid; i < 64 * 64; i += 256) {
        int r = i >> 6, d = i & 63;
        Qt[d * PAD + r] = Qg[(size_t)r * Dq + d] * 0.125f;
    }

    float o[4][4];
    float mrow[4], lrow[4];
#pragma unroll
    for (int i = 0; i < 4; ++i) {
        mrow[i] = -INFINITY; lrow[i] = 0.f;
#pragma unroll
        for (int j = 0; j < 4; ++j) o[i][j] = 0.f;
    }

    __syncthreads();

    for (int kb = 0; kb <= qb; ++kb) {
        const float* Kg = K + ((size_t)b * Tq + kb * KT) * Dq + h * DKq;
        const float* Vg = V + ((size_t)b * Tq + kb * KT) * Dq + h * DKq;

        // K transposed (scalar, coalesced global, 4-way smem store conflicts OK)
        for (int i = tid; i < 64 * 64; i += 256) {
            int r = i >> 6, d = i & 63;
            Kt[d * PAD + r] = Kg[(size_t)r * Dq + d];
        }
        // V natural, vectorized
        for (int i = tid; i < 64 * 16; i += 256) {
            int r = i >> 4, d4 = (i & 15) * 4;
            float4 vv = *(const float4*)(Vg + (size_t)r * Dq + d4);
            *(float4*)&Vs[r * PAD + d4] = vv;
        }
        __syncthreads();

        // S = Qscaled @ K^T  (each thread: 4x4), all LDS.128
        float s[4][4];
#pragma unroll
        for (int i = 0; i < 4; ++i)
#pragma unroll
            for (int j = 0; j < 4; ++j) s[i][j] = 0.f;

#pragma unroll 4
        for (int d = 0; d < 64; ++d) {
            float4 qa = *(const float4*)&Qt[d * PAD + ty * 4];
            float4 kv = *(const float4*)&Kt[d * PAD + tx * 4];
            float ra[4] = {qa.x, qa.y, qa.z, qa.w};
            float rb[4] = {kv.x, kv.y, kv.z, kv.w};
#pragma unroll
            for (int i = 0; i < 4; ++i)
#pragma unroll
                for (int j = 0; j < 4; ++j)
                    s[i][j] += ra[i] * rb[j];
        }

        // causal mask on the diagonal block
        if (kb == qb) {
#pragma unroll
            for (int i = 0; i < 4; ++i) {
                int qi = ty * 4 + i;
#pragma unroll
                for (int j = 0; j < 4; ++j)
                    if (tx * 4 + j > qi) s[i][j] = -INFINITY;
            }
        }

        // register online softmax; rows are owned by the 16 tx-lanes of a half-warp
#pragma unroll
        for (int i = 0; i < 4; ++i) {
            float rmax = fmaxf(fmaxf(s[i][0], s[i][1]), fmaxf(s[i][2], s[i][3]));
#pragma unroll
            for (int off = 1; off < 16; off <<= 1)
                rmax = fmaxf(rmax, __shfl_xor_sync(0xffffffffu, rmax, off));

            float mnew  = fmaxf(mrow[i], rmax);
            float alpha = __expf(mrow[i] - mnew);   // 0 on first block
            float p0 = __expf(s[i][0] - mnew);
            float p1 = __expf(s[i][1] - mnew);
            float p2 = __expf(s[i][2] - mnew);
            float p3 = __expf(s[i][3] - mnew);
            float rsum = (p0 + p1) + (p2 + p3);
#pragma unroll
            for (int off = 1; off < 16; off <<= 1)
                rsum += __shfl_xor_sync(0xffffffffu, rsum, off);

            mrow[i] = mnew;
            lrow[i] = lrow[i] * alpha + rsum;
#pragma unroll
            for (int j = 0; j < 4; ++j) o[i][j] *= alpha;

            float4 pv = make_float4(p0, p1, p2, p3);
            *(float4*)&Ps[(ty * 4 + i) * PAD + tx * 4] = pv;
        }
        __syncthreads();

        // O += P @ V
#pragma unroll 4
        for (int k = 0; k < 64; ++k) {
            float4 vv = *(const float4*)&Vs[k * PAD + tx * 4];
            float rb[4] = {vv.x, vv.y, vv.z, vv.w};
            float pr[4];
#pragma unroll
            for (int i = 0; i < 4; ++i) pr[i] = Ps[(ty * 4 + i) * PAD + k];
#pragma unroll
            for (int i = 0; i < 4; ++i)
#pragma unroll
                for (int j = 0; j < 4; ++j)
                    o[i][j] += pr[i] * rb[j];
        }
        __syncthreads();   // protect Kt/Vs/Ps before next iteration's loads
    }

    // write context (B,T,D) with head offset
    float* Cg = Ctx + ((size_t)b * Tq + qb * QT) * Dq + h * DKq;
#pragma unroll
    for (int i = 0; i < 4; ++i) {
        float inv = 1.f / lrow[i];
        float4 ov;
        ov.x = o[i][0] * inv; ov.y = o[i][1] * inv;
        ov.z = o[i][2] * inv; ov.w = o[i][3] * inv;
        *(float4*)(Cg + (size_t)(ty * 4 + i) * Dq + tx * 4) = ov;
    }
}

// ---------------- launch ----------------------------------------------------
extern "C" void kernel_launch(void* const* d_in, const int* in_sizes, int n_in,
                              void* d_out, int out_size)
{
    const float* x  = (const float*)d_in[0];
    const float* Wq = (const float*)d_in[1];
    const float* bq = (const float*)d_in[2];
    const float* Wk = (const float*)d_in[3];
    const float* bk = (const float*)d_in[4];
    const float* Wv = (const float*)d_in[5];
    const float* bv = (const float*)d_in[6];
    const float* Wo = (const float*)d_in[7];
    const float* bo = (const float*)d_in[8];
    float* out = (float*)d_out;

    float *pQ, *pK, *pV, *pC;
    cudaGetSymbolAddress((void**)&pQ, g_Q);
    cudaGetSymbolAddress((void**)&pK, g_K);
    cudaGetSymbolAddress((void**)&pV, g_V);
    cudaGetSymbolAddress((void**)&pC, g_C);

    const int SMEM_ATTN = 4 * 64 * PAD * (int)sizeof(float);
    cudaFuncSetAttribute(attn_kernel,
                         cudaFuncAttributeMaxDynamicSharedMemorySize, SMEM_ATTN);

    dim3 bGemm(256);

    // fused Q/K/V projections (one launch, 768 CTAs)
    dim3 gQKV(Dq / BN, Mq / BM, 3);
    sgemm_qkv_kernel<<<gQKV, bGemm>>>(x, Wq, bq, Wk, bk, Wv, bv, pQ, pK, pV);

    // attention
    dim3 gAttn(Tq / QT, Hq, Bq);    // (32, 16, 2)
    attn_kernel<<<gAttn, 256, SMEM_ATTN>>>(pQ, pK, pV, pC);

    // output projection
    dim3 gGemm(Dq / BN, Mq / BM);
    sgemm_bias_kernel<<<gGemm, bGemm>>>(pC, Wo, bo, out, Mq, Dq, Dq);
}

// round 3
// speedup vs baseline: 1.5915x; 1.5404x over previous
#include <cuda_runtime.h>
#include <cuda_bf16.h>
#include <math.h>
#include <stdint.h>

// Problem constants
#define Bq 2
#define Tq 2048
#define Dq 1024
#define Hq 16
#define DKq 64
#define Mq (Bq*Tq)   // 4096

// ---------------- scratch (device globals; no allocation allowed) ----------
__device__ float g_Q[Mq * Dq];
__device__ float g_K[Mq * Dq];
__device__ float g_V[Mq * Dq];
__device__ float g_C[Mq * Dq];

// ---------------- tf32 helpers ----------------------------------------------
__device__ __forceinline__ uint32_t f2tf32(float f) {
    uint32_t r;
    asm volatile("cvt.rna.tf32.f32 %0, %1;" : "=r"(r) : "f"(f));
    return r;
}

__device__ __forceinline__ void mma_tf32(float c[4],
                                         uint32_t a0, uint32_t a1, uint32_t a2, uint32_t a3,
                                         uint32_t b0, uint32_t b1) {
    asm volatile(
        "mma.sync.aligned.m16n8k8.row.col.f32.tf32.tf32.f32 "
        "{%0,%1,%2,%3}, {%4,%5,%6,%7}, {%8,%9}, {%0,%1,%2,%3};"
        : "+f"(c[0]), "+f"(c[1]), "+f"(c[2]), "+f"(c[3])
        : "r"(a0), "r"(a1), "r"(a2), "r"(a3), "r"(b0), "r"(b1));
}

// ---------------- TF32 GEMM: Y = X @ W + bias --------------------------------
// X: (M,K) row-major fp32, W: (K,N) row-major fp32, Y: (M,N) fp32.
// CTA tile 128x128, BK=16. 256 threads = 8 warps, warp tile 64x32.
// Fragments per PTX m16n8k8.row.col tf32 layout.
#define GBM 128
#define GBN 128
#define GBK 16
#define SMP 136   // smem row stride (floats): 128+8 -> conflict-free frag loads

__device__ __forceinline__
void tf32_gemm_body(const float* __restrict__ X,
                    const float* __restrict__ W,
                    const float* __restrict__ bias,
                    float* __restrict__ Y,
                    int M, int N, int K,
                    int bm, int bn)
{
    __shared__ uint32_t As[GBK][SMP];   // As[k][m]  (tf32 bits)
    __shared__ uint32_t Bs[GBK][SMP];   // Bs[k][n]  (tf32 bits)

    const int tid  = threadIdx.x;
    const int wid  = tid >> 5;
    const int lane = tid & 31;
    const int gr   = lane >> 2;   // 0..7
    const int tc   = lane & 3;    // 0..3

    const int wm = wid & 1;       // 0..1  (64 rows)
    const int wn = wid >> 1;      // 0..3  (32 cols)

    // global load mapping
    const int a_r  = tid >> 1;           // 0..127
    const int a_kc = (tid & 1) * 8;      // 0 or 8
    const int b_r  = tid >> 4;           // 0..15
    const int b_c  = (tid & 15) * 4;     // 0..60

    const float* Xp = X + (size_t)(bm * GBM) * K;
    const float* Wp = W + (size_t)bn * GBN;

    float acc[4][4][4];   // [mt][nt][frag]
#pragma unroll
    for (int i = 0; i < 4; ++i)
#pragma unroll
        for (int j = 0; j < 4; ++j)
#pragma unroll
            for (int f = 0; f < 4; ++f) acc[i][j][f] = 0.f;

    for (int k0 = 0; k0 < K; k0 += GBK) {
        // A tile: 128 rows x 16 k, transposed into As[k][m]
        {
            float4 v0 = *(const float4*)(Xp + (size_t)a_r * K + k0 + a_kc);
            float4 v1 = *(const float4*)(Xp + (size_t)a_r * K + k0 + a_kc + 4);
            As[a_kc + 0][a_r] = f2tf32(v0.x);
            As[a_kc + 1][a_r] = f2tf32(v0.y);
            As[a_kc + 2][a_r] = f2tf32(v0.z);
            As[a_kc + 3][a_r] = f2tf32(v0.w);
            As[a_kc + 4][a_r] = f2tf32(v1.x);
            As[a_kc + 5][a_r] = f2tf32(v1.y);
            As[a_kc + 6][a_r] = f2tf32(v1.z);
            As[a_kc + 7][a_r] = f2tf32(v1.w);
        }
        // B tile: 16 k x 128 n, natural layout
#pragma unroll
        for (int half = 0; half < 2; ++half) {
            int c = b_c + half * 64;
            float4 v = *(const float4*)(Wp + (size_t)(k0 + b_r) * N + c);
            uint4 u;
            u.x = f2tf32(v.x); u.y = f2tf32(v.y);
            u.z = f2tf32(v.z); u.w = f2tf32(v.w);
            *(uint4*)&Bs[b_r][c] = u;
        }
        __syncthreads();

#pragma unroll
        for (int ks = 0; ks < GBK; ks += 8) {
            uint32_t af[4][4];
            uint32_t bf[4][2];
#pragma unroll
            for (int mt = 0; mt < 4; ++mt) {
                int m0 = wm * 64 + mt * 16;
                af[mt][0] = As[ks + tc][m0 + gr];
                af[mt][1] = As[ks + tc][m0 + gr + 8];
                af[mt][2] = As[ks + tc + 4][m0 + gr];
                af[mt][3] = As[ks + tc + 4][m0 + gr + 8];
            }
#pragma unroll
            for (int nt = 0; nt < 4; ++nt) {
                int n0 = wn * 32 + nt * 8;
                bf[nt][0] = Bs[ks + tc][n0 + gr];
                bf[nt][1] = Bs[ks + tc + 4][n0 + gr];
            }
#pragma unroll
            for (int mt = 0; mt < 4; ++mt)
#pragma unroll
                for (int nt = 0; nt < 4; ++nt)
                    mma_tf32(acc[mt][nt],
                             af[mt][0], af[mt][1], af[mt][2], af[mt][3],
                             bf[nt][0], bf[nt][1]);
        }
        __syncthreads();
    }

    // epilogue: c0,c1 -> (row, col..col+1); c2,c3 -> (row+8, ...)
#pragma unroll
    for (int mt = 0; mt < 4; ++mt) {
        int row = bm * GBM + wm * 64 + mt * 16 + gr;
#pragma unroll
        for (int nt = 0; nt < 4; ++nt) {
            int col = bn * GBN + wn * 32 + nt * 8 + 2 * tc;
            float b0 = bias[col], b1 = bias[col + 1];
            float2 lo, hi;
            lo.x = acc[mt][nt][0] + b0; lo.y = acc[mt][nt][1] + b1;
            hi.x = acc[mt][nt][2] + b0; hi.y = acc[mt][nt][3] + b1;
            *(float2*)(Y + (size_t)row * N + col)       = lo;
            *(float2*)(Y + (size_t)(row + 8) * N + col) = hi;
        }
    }
}

__global__ __launch_bounds__(256)
void tf32_gemm_kernel(const float* __restrict__ X,
                      const float* __restrict__ W,
                      const float* __restrict__ bias,
                      float* __restrict__ Y,
                      int M, int N, int K)
{
    tf32_gemm_body(X, W, bias, Y, M, N, K, blockIdx.y, blockIdx.x);
}

// Fused Q/K/V projections: gridDim.z selects which projection.
__global__ __launch_bounds__(256)
void tf32_qkv_kernel(const float* __restrict__ X,
                     const float* __restrict__ Wq, const float* __restrict__ bqv,
                     const float* __restrict__ Wk, const float* __restrict__ bkv,
                     const float* __restrict__ Wv, const float* __restrict__ bvv,
                     float* __restrict__ Qo, float* __restrict__ Ko, float* __restrict__ Vo)
{
    const float* W; const float* bias; float* Y;
    if (blockIdx.z == 0)      { W = Wq; bias = bqv; Y = Qo; }
    else if (blockIdx.z == 1) { W = Wk; bias = bkv; Y = Ko; }
    else                      { W = Wv; bias = bvv; Y = Vo; }
    tf32_gemm_body(X, W, bias, Y, Mq, Dq, Dq, blockIdx.y, blockIdx.x);
}

// ---------------- Flash attention (fp32, causal) ----------------------------
// Grid: (T/64, H, B). 256 threads. 64x64 Q tile, 64x64 K/V tiles.
// Register-resident online softmax with shfl row reductions.
#define QT 64
#define KT 64
#define PAD 68

__global__ __launch_bounds__(256, 2)
void attn_kernel(const float* __restrict__ Q,
                 const float* __restrict__ K,
                 const float* __restrict__ V,
                 float* __restrict__ Ctx)
{
    extern __shared__ float sm[];
    float* Qt = sm;                // [64][PAD]  Qt[d][r], pre-scaled
    float* Kt = Qt + 64 * PAD;     // [64][PAD]  Kt[d][c]
    float* Vs = Kt + 64 * PAD;     // [64][PAD]  Vs[k][d]
    float* Ps = Vs + 64 * PAD;     // [64][PAD]  probs

    const int b  = blockIdx.z;
    const int h  = blockIdx.y;
    const int qb = blockIdx.x;
    const int tid = threadIdx.x;
    const int tx = tid & 15;   // col group (0..15)
    const int ty = tid >> 4;   // row group (0..15)

    const float* Qg = Q + ((size_t)b * Tq + qb * QT) * Dq + h * DKq;

    for (int i = tid; i < 64 * 64; i += 256) {
        int r = i >> 6, d = i & 63;
        Qt[d * PAD + r] = Qg[(size_t)r * Dq + d] * 0.125f;
    }

    float o[4][4];
    float mrow[4], lrow[4];
#pragma unroll
    for (int i = 0; i < 4; ++i) {
        mrow[i] = -INFINITY; lrow[i] = 0.f;
#pragma unroll
        for (int j = 0; j < 4; ++j) o[i][j] = 0.f;
    }

    __syncthreads();

    for (int kb = 0; kb <= qb; ++kb) {
        const float* Kg = K + ((size_t)b * Tq + kb * KT) * Dq + h * DKq;
        const float* Vg = V + ((size_t)b * Tq + kb * KT) * Dq + h * DKq;

        for (int i = tid; i < 64 * 64; i += 256) {
            int r = i >> 6, d = i & 63;
            Kt[d * PAD + r] = Kg[(size_t)r * Dq + d];
        }
        for (int i = tid; i < 64 * 16; i += 256) {
            int r = i >> 4, d4 = (i & 15) * 4;
            float4 vv = *(const float4*)(Vg + (size_t)r * Dq + d4);
            *(float4*)&Vs[r * PAD + d4] = vv;
        }
        __syncthreads();

        float s[4][4];
#pragma unroll
        for (int i = 0; i < 4; ++i)
#pragma unroll
            for (int j = 0; j < 4; ++j) s[i][j] = 0.f;

#pragma unroll 4
        for (int d = 0; d < 64; ++d) {
            float4 qa = *(const float4*)&Qt[d * PAD + ty * 4];
            float4 kv = *(const float4*)&Kt[d * PAD + tx * 4];
            float ra[4] = {qa.x, qa.y, qa.z, qa.w};
            float rb[4] = {kv.x, kv.y, kv.z, kv.w};
#pragma unroll
            for (int i = 0; i < 4; ++i)
#pragma unroll
                for (int j = 0; j < 4; ++j)
                    s[i][j] += ra[i] * rb[j];
        }

        if (kb == qb) {
#pragma unroll
            for (int i = 0; i < 4; ++i) {
                int qi = ty * 4 + i;
#pragma unroll
                for (int j = 0; j < 4; ++j)
                    if (tx * 4 + j > qi) s[i][j] = -INFINITY;
            }
        }

#pragma unroll
        for (int i = 0; i < 4; ++i) {
            float rmax = fmaxf(fmaxf(s[i][0], s[i][1]), fmaxf(s[i][2], s[i][3]));
#pragma unroll
            for (int off = 1; off < 16; off <<= 1)
                rmax = fmaxf(rmax, __shfl_xor_sync(0xffffffffu, rmax, off));

            float mnew  = fmaxf(mrow[i], rmax);
            float alpha = __expf(mrow[i] - mnew);
            float p0 = __expf(s[i][0] - mnew);
            float p1 = __expf(s[i][1] - mnew);
            float p2 = __expf(s[i][2] - mnew);
            float p3 = __expf(s[i][3] - mnew);
            float rsum = (p0 + p1) + (p2 + p3);
#pragma unroll
            for (int off = 1; off < 16; off <<= 1)
                rsum += __shfl_xor_sync(0xffffffffu, rsum, off);

            mrow[i] = mnew;
            lrow[i] = lrow[i] * alpha + rsum;
#pragma unroll
            for (int j = 0; j < 4; ++j) o[i][j] *= alpha;

            float4 pv = make_float4(p0, p1, p2, p3);
            *(float4*)&Ps[(ty * 4 + i) * PAD + tx * 4] = pv;
        }
        __syncthreads();

#pragma unroll 4
        for (int k = 0; k < 64; ++k) {
            float4 vv = *(const float4*)&Vs[k * PAD + tx * 4];
            float rb[4] = {vv.x, vv.y, vv.z, vv.w};
            float pr[4];
#pragma unroll
            for (int i = 0; i < 4; ++i) pr[i] = Ps[(ty * 4 + i) * PAD + k];
#pragma unroll
            for (int i = 0; i < 4; ++i)
#pragma unroll
                for (int j = 0; j < 4; ++j)
                    o[i][j] += pr[i] * rb[j];
        }
        __syncthreads();
    }

    float* Cg = Ctx + ((size_t)b * Tq + qb * QT) * Dq + h * DKq;
#pragma unroll
    for (int i = 0; i < 4; ++i) {
        float inv = 1.f / lrow[i];
        float4 ov;
        ov.x = o[i][0] * inv; ov.y = o[i][1] * inv;
        ov.z = o[i][2] * inv; ov.w = o[i][3] * inv;
        *(float4*)(Cg + (size_t)(ty * 4 + i) * Dq + tx * 4) = ov;
    }
}

// ---------------- launch ----------------------------------------------------
extern "C" void kernel_launch(void* const* d_in, const int* in_sizes, int n_in,
                              void* d_out, int out_size)
{
    const float* x  = (const float*)d_in[0];
    const float* Wq = (const float*)d_in[1];
    const float* bq = (const float*)d_in[2];
    const float* Wk = (const float*)d_in[3];
    const float* bk = (const float*)d_in[4];
    const float* Wv = (const float*)d_in[5];
    const float* bv = (const float*)d_in[6];
    const float* Wo = (const float*)d_in[7];
    const float* bo = (const float*)d_in[8];
    float* out = (float*)d_out;

    float *pQ, *pK, *pV, *pC;
    cudaGetSymbolAddress((void**)&pQ, g_Q);
    cudaGetSymbolAddress((void**)&pK, g_K);
    cudaGetSymbolAddress((void**)&pV, g_V);
    cudaGetSymbolAddress((void**)&pC, g_C);

    const int SMEM_ATTN = 4 * 64 * PAD * (int)sizeof(float);
    cudaFuncSetAttribute(attn_kernel,
                         cudaFuncAttributeMaxDynamicSharedMemorySize, SMEM_ATTN);

    dim3 bGemm(256);

    // fused Q/K/V projections (tf32 tensor cores)
    dim3 gQKV(Dq / GBN, Mq / GBM, 3);
    tf32_qkv_kernel<<<gQKV, bGemm>>>(x, Wq, bq, Wk, bk, Wv, bv, pQ, pK, pV);

    // attention (fp32)
    dim3 gAttn(Tq / QT, Hq, Bq);    // (32, 16, 2)
    attn_kernel<<<gAttn, 256, SMEM_ATTN>>>(pQ, pK, pV, pC);

    // output projection (tf32 tensor cores)
    dim3 gGemm(Dq / GBN, Mq / GBM);
    tf32_gemm_kernel<<<gGemm, bGemm>>>(pC, Wo, bo, out, Mq, Dq, Dq);
}

// round 4
// speedup vs baseline: 2.1053x; 1.3229x over previous
#include <cuda_runtime.h>
#include <cuda_bf16.h>
#include <math.h>
#include <stdint.h>

// Problem constants
#define Bq 2
#define Tq 2048
#define Dq 1024
#define Hq 16
#define DKq 64
#define Mq (Bq*Tq)   // 4096

// ---------------- scratch (device globals; no allocation allowed) ----------
__device__ float g_Q[Mq * Dq];
__device__ float g_K[Mq * Dq];
__device__ float g_V[Mq * Dq];
__device__ float g_C[Mq * Dq];

// ---------------- tf32 helpers ----------------------------------------------
__device__ __forceinline__ uint32_t f2tf32(float f) {
    uint32_t r;
    asm volatile("cvt.rna.tf32.f32 %0, %1;" : "=r"(r) : "f"(f));
    return r;
}

__device__ __forceinline__ void mma_tf32(float c[4],
                                         uint32_t a0, uint32_t a1, uint32_t a2, uint32_t a3,
                                         uint32_t b0, uint32_t b1) {
    asm volatile(
        "mma.sync.aligned.m16n8k8.row.col.f32.tf32.tf32.f32 "
        "{%0,%1,%2,%3}, {%4,%5,%6,%7}, {%8,%9}, {%0,%1,%2,%3};"
        : "+f"(c[0]), "+f"(c[1]), "+f"(c[2]), "+f"(c[3])
        : "r"(a0), "r"(a1), "r"(a2), "r"(a3), "r"(b0), "r"(b1));
}

// ---------------- TF32 GEMM: Y = X @ W + bias --------------------------------
#define GBM 128
#define GBN 128
#define GBK 16
#define SMP 136

__device__ __forceinline__
void tf32_gemm_body(const float* __restrict__ X,
                    const float* __restrict__ W,
                    const float* __restrict__ bias,
                    float* __restrict__ Y,
                    int M, int N, int K,
                    int bm, int bn)
{
    __shared__ uint32_t As[GBK][SMP];
    __shared__ uint32_t Bs[GBK][SMP];

    const int tid  = threadIdx.x;
    const int wid  = tid >> 5;
    const int lane = tid & 31;
    const int gr   = lane >> 2;
    const int tc   = lane & 3;

    const int wm = wid & 1;
    const int wn = wid >> 1;

    const int a_r  = tid >> 1;
    const int a_kc = (tid & 1) * 8;
    const int b_r  = tid >> 4;
    const int b_c  = (tid & 15) * 4;

    const float* Xp = X + (size_t)(bm * GBM) * K;
    const float* Wp = W + (size_t)bn * GBN;

    float acc[4][4][4];
#pragma unroll
    for (int i = 0; i < 4; ++i)
#pragma unroll
        for (int j = 0; j < 4; ++j)
#pragma unroll
            for (int f = 0; f < 4; ++f) acc[i][j][f] = 0.f;

    for (int k0 = 0; k0 < K; k0 += GBK) {
        {
            float4 v0 = *(const float4*)(Xp + (size_t)a_r * K + k0 + a_kc);
            float4 v1 = *(const float4*)(Xp + (size_t)a_r * K + k0 + a_kc + 4);
            As[a_kc + 0][a_r] = f2tf32(v0.x);
            As[a_kc + 1][a_r] = f2tf32(v0.y);
            As[a_kc + 2][a_r] = f2tf32(v0.z);
            As[a_kc + 3][a_r] = f2tf32(v0.w);
            As[a_kc + 4][a_r] = f2tf32(v1.x);
            As[a_kc + 5][a_r] = f2tf32(v1.y);
            As[a_kc + 6][a_r] = f2tf32(v1.z);
            As[a_kc + 7][a_r] = f2tf32(v1.w);
        }
#pragma unroll
        for (int half = 0; half < 2; ++half) {
            int c = b_c + half * 64;
            float4 v = *(const float4*)(Wp + (size_t)(k0 + b_r) * N + c);
            uint4 u;
            u.x = f2tf32(v.x); u.y = f2tf32(v.y);
            u.z = f2tf32(v.z); u.w = f2tf32(v.w);
            *(uint4*)&Bs[b_r][c] = u;
        }
        __syncthreads();

#pragma unroll
        for (int ks = 0; ks < GBK; ks += 8) {
            uint32_t af[4][4];
            uint32_t bf[4][2];
#pragma unroll
            for (int mt = 0; mt < 4; ++mt) {
                int m0 = wm * 64 + mt * 16;
                af[mt][0] = As[ks + tc][m0 + gr];
                af[mt][1] = As[ks + tc][m0 + gr + 8];
                af[mt][2] = As[ks + tc + 4][m0 + gr];
                af[mt][3] = As[ks + tc + 4][m0 + gr + 8];
            }
#pragma unroll
            for (int nt = 0; nt < 4; ++nt) {
                int n0 = wn * 32 + nt * 8;
                bf[nt][0] = Bs[ks + tc][n0 + gr];
                bf[nt][1] = Bs[ks + tc + 4][n0 + gr];
            }
#pragma unroll
            for (int mt = 0; mt < 4; ++mt)
#pragma unroll
                for (int nt = 0; nt < 4; ++nt)
                    mma_tf32(acc[mt][nt],
                             af[mt][0], af[mt][1], af[mt][2], af[mt][3],
                             bf[nt][0], bf[nt][1]);
        }
        __syncthreads();
    }

#pragma unroll
    for (int mt = 0; mt < 4; ++mt) {
        int row = bm * GBM + wm * 64 + mt * 16 + gr;
#pragma unroll
        for (int nt = 0; nt < 4; ++nt) {
            int col = bn * GBN + wn * 32 + nt * 8 + 2 * tc;
            float b0 = bias[col], b1 = bias[col + 1];
            float2 lo, hi;
            lo.x = acc[mt][nt][0] + b0; lo.y = acc[mt][nt][1] + b1;
            hi.x = acc[mt][nt][2] + b0; hi.y = acc[mt][nt][3] + b1;
            *(float2*)(Y + (size_t)row * N + col)       = lo;
            *(float2*)(Y + (size_t)(row + 8) * N + col) = hi;
        }
    }
}

__global__ __launch_bounds__(256)
void tf32_gemm_kernel(const float* __restrict__ X,
                      const float* __restrict__ W,
                      const float* __restrict__ bias,
                      float* __restrict__ Y,
                      int M, int N, int K)
{
    tf32_gemm_body(X, W, bias, Y, M, N, K, blockIdx.y, blockIdx.x);
}

__global__ __launch_bounds__(256)
void tf32_qkv_kernel(const float* __restrict__ X,
                     const float* __restrict__ Wq, const float* __restrict__ bqv,
                     const float* __restrict__ Wk, const float* __restrict__ bkv,
                     const float* __restrict__ Wv, const float* __restrict__ bvv,
                     float* __restrict__ Qo, float* __restrict__ Ko, float* __restrict__ Vo)
{
    const float* W; const float* bias; float* Y;
    if (blockIdx.z == 0)      { W = Wq; bias = bqv; Y = Qo; }
    else if (blockIdx.z == 1) { W = Wk; bias = bkv; Y = Ko; }
    else                      { W = Wv; bias = bvv; Y = Vo; }
    tf32_gemm_body(X, W, bias, Y, Mq, Dq, Dq, blockIdx.y, blockIdx.x);
}

// ---------------- Tensor-core flash attention (tf32 split, causal) ----------
// Grid: (T/128, H, B). 256 threads = 8 warps; warp w owns Q rows [w*16, w*16+16).
// S = Qh*Kh + Ql*Kh + Qh*Kl (3 MMAs ~ fp32); O += P*Vh + P*Vl (2 MMAs).
#define AQT 128
#define AKT 64
#define APAD 68

__global__ __launch_bounds__(256, 1)
void attn_tc_kernel(const float* __restrict__ Q,
                    const float* __restrict__ K,
                    const float* __restrict__ V,
                    float* __restrict__ Ctx)
{
    extern __shared__ uint32_t smu[];
    uint32_t* Ks_h = smu;                     // [64][APAD]
    uint32_t* Ks_l = Ks_h + 64 * APAD;        // [64][APAD]
    uint32_t* Vt_h = Ks_l + 64 * APAD;        // [64][APAD]  Vt[d][key]
    uint32_t* Vt_l = Vt_h + 64 * APAD;        // [64][APAD]
    uint32_t* Ps   = Vt_l + 64 * APAD;        // [128][APAD] tf32 probs
    float*    Qst  = (float*)Ps;              // Q staging (aliased, used pre-loop)

    const int b  = blockIdx.z;
    const int h  = blockIdx.y;
    const int qb = blockIdx.x;
    const int tid  = threadIdx.x;
    const int wid  = tid >> 5;
    const int lane = tid & 31;
    const int gr   = lane >> 2;   // 0..7
    const int tc   = lane & 3;    // 0..3

    const int qrow0 = qb * AQT;
    const float* Qg = Q + ((size_t)b * Tq + qrow0) * Dq + h * DKq;

    // stage Q (scaled) then build register-resident hi/lo A-fragments
    for (int i = tid; i < AQT * 64; i += 256) {
        int r = i >> 6, d = i & 63;
        Qst[r * APAD + d] = Qg[(size_t)r * Dq + d] * 0.125f;
    }
    __syncthreads();

    uint32_t qh[8][4], ql[8][4];
    {
        const int rbase = wid * 16;
#pragma unroll
        for (int kk = 0; kk < 8; ++kk) {
#pragma unroll
            for (int f = 0; f < 4; ++f) {
                int r = rbase + gr + (f & 1) * 8;
                int c = kk * 8 + tc + (f >> 1) * 4;
                float v = Qst[r * APAD + c];
                uint32_t hi = f2tf32(v);
                qh[kk][f] = hi;
                ql[kk][f] = f2tf32(v - __uint_as_float(hi));
            }
        }
    }
    __syncthreads();   // done with Qst before Ps reuse

    float oacc[8][4];
#pragma unroll
    for (int n = 0; n < 8; ++n)
#pragma unroll
        for (int f = 0; f < 4; ++f) oacc[n][f] = 0.f;
    float m0 = -INFINITY, m1 = -INFINITY, l0 = 0.f, l1 = 0.f;

    const int row0g = qrow0 + wid * 16 + gr;
    const int row1g = row0g + 8;
    const int kbmax = (qb + 1) * 2;

    for (int kb = 0; kb < kbmax; ++kb) {
        const float* Kg = K + ((size_t)b * Tq + kb * AKT) * Dq + h * DKq;
        const float* Vg = V + ((size_t)b * Tq + kb * AKT) * Dq + h * DKq;

        // cooperative K/V load with tf32 hi/lo split; V transposed
        for (int i = tid; i < AKT * 64; i += 256) {
            int r = i >> 6, d = i & 63;
            float kv = Kg[(size_t)r * Dq + d];
            uint32_t khi = f2tf32(kv);
            Ks_h[r * APAD + d] = khi;
            Ks_l[r * APAD + d] = f2tf32(kv - __uint_as_float(khi));
            float vv = Vg[(size_t)r * Dq + d];
            uint32_t vhi = f2tf32(vv);
            Vt_h[d * APAD + r] = vhi;
            Vt_l[d * APAD + r] = f2tf32(vv - __uint_as_float(vhi));
        }
        __syncthreads();

        const bool active = (kb * AKT <= qrow0 + wid * 16 + 15);

        if (active) {
            // ---- S = Q @ K^T (3-term tf32 split) ----
            float sacc[8][4];
#pragma unroll
            for (int n = 0; n < 8; ++n)
#pragma unroll
                for (int f = 0; f < 4; ++f) sacc[n][f] = 0.f;

#pragma unroll
            for (int kk = 0; kk < 8; ++kk) {
#pragma unroll
                for (int n = 0; n < 8; ++n) {
                    int base = (n * 8 + gr) * APAD + kk * 8 + tc;
                    uint32_t bh0 = Ks_h[base], bh1 = Ks_h[base + 4];
                    uint32_t bl0 = Ks_l[base], bl1 = Ks_l[base + 4];
                    mma_tf32(sacc[n], qh[kk][0], qh[kk][1], qh[kk][2], qh[kk][3], bh0, bh1);
                    mma_tf32(sacc[n], ql[kk][0], ql[kk][1], ql[kk][2], ql[kk][3], bh0, bh1);
                    mma_tf32(sacc[n], qh[kk][0], qh[kk][1], qh[kk][2], qh[kk][3], bl0, bl1);
                }
            }

            // ---- causal mask (only when block can cross the diagonal) ----
            if (kb * AKT + AKT - 1 > row0g) {
#pragma unroll
                for (int n = 0; n < 8; ++n) {
                    int colg = kb * AKT + n * 8 + 2 * tc;
                    if (colg     > row0g) sacc[n][0] = -INFINITY;
                    if (colg + 1 > row0g) sacc[n][1] = -INFINITY;
                    if (colg     > row1g) sacc[n][2] = -INFINITY;
                    if (colg + 1 > row1g) sacc[n][3] = -INFINITY;
                }
            }

            // ---- online softmax (rows warp-local, quad shfl reduce) ----
            float rmax0 = -INFINITY, rmax1 = -INFINITY;
#pragma unroll
            for (int n = 0; n < 8; ++n) {
                rmax0 = fmaxf(rmax0, fmaxf(sacc[n][0], sacc[n][1]));
                rmax1 = fmaxf(rmax1, fmaxf(sacc[n][2], sacc[n][3]));
            }
#pragma unroll
            for (int off = 1; off < 4; off <<= 1) {
                rmax0 = fmaxf(rmax0, __shfl_xor_sync(0xffffffffu, rmax0, off));
                rmax1 = fmaxf(rmax1, __shfl_xor_sync(0xffffffffu, rmax1, off));
            }

            float mn0 = fmaxf(m0, rmax0);
            float mn1 = fmaxf(m1, rmax1);
            float alpha0 = __expf(m0 - mn0);
            float alpha1 = __expf(m1 - mn1);

            float rsum0 = 0.f, rsum1 = 0.f;
            const int prow0 = (wid * 16 + gr) * APAD;
            const int prow1 = prow0 + 8 * APAD;
#pragma unroll
            for (int n = 0; n < 8; ++n) {
                float p00 = __expf(sacc[n][0] - mn0);
                float p01 = __expf(sacc[n][1] - mn0);
                float p10 = __expf(sacc[n][2] - mn1);
                float p11 = __expf(sacc[n][3] - mn1);
                uint32_t t00 = f2tf32(p00), t01 = f2tf32(p01);
                uint32_t t10 = f2tf32(p10), t11 = f2tf32(p11);
                // sum the rounded values so l matches PV exactly
                rsum0 += __uint_as_float(t00) + __uint_as_float(t01);
                rsum1 += __uint_as_float(t10) + __uint_as_float(t11);
                int c = n * 8 + 2 * tc;
                Ps[prow0 + c]     = t00;
                Ps[prow0 + c + 1] = t01;
                Ps[prow1 + c]     = t10;
                Ps[prow1 + c + 1] = t11;
            }
#pragma unroll
            for (int off = 1; off < 4; off <<= 1) {
                rsum0 += __shfl_xor_sync(0xffffffffu, rsum0, off);
                rsum1 += __shfl_xor_sync(0xffffffffu, rsum1, off);
            }

            m0 = mn0; m1 = mn1;
            l0 = l0 * alpha0 + rsum0;
            l1 = l1 * alpha1 + rsum1;
#pragma unroll
            for (int n = 0; n < 8; ++n) {
                oacc[n][0] *= alpha0; oacc[n][1] *= alpha0;
                oacc[n][2] *= alpha1; oacc[n][3] *= alpha1;
            }
            __syncwarp();   // Ps visibility is warp-local (rows owned by warp)

            // ---- O += P @ V (2-term split on V) ----
#pragma unroll
            for (int kk = 0; kk < 8; ++kk) {
                int pc = kk * 8 + tc;
                uint32_t a0 = Ps[prow0 + pc];
                uint32_t a1 = Ps[prow1 + pc];
                uint32_t a2 = Ps[prow0 + pc + 4];
                uint32_t a3 = Ps[prow1 + pc + 4];
#pragma unroll
                for (int n = 0; n < 8; ++n) {
                    int base = (n * 8 + gr) * APAD + kk * 8 + tc;
                    uint32_t bh0 = Vt_h[base], bh1 = Vt_h[base + 4];
                    uint32_t bl0 = Vt_l[base], bl1 = Vt_l[base + 4];
                    mma_tf32(oacc[n], a0, a1, a2, a3, bh0, bh1);
                    mma_tf32(oacc[n], a0, a1, a2, a3, bl0, bl1);
                }
            }
        }
        __syncthreads();   // protect Ks/Vt before next block's loads
    }

    // epilogue
    float inv0 = 1.f / l0;
    float inv1 = 1.f / l1;
    float* Cg = Ctx + ((size_t)b * Tq + qrow0) * Dq + h * DKq;
    const int r0 = wid * 16 + gr;
#pragma unroll
    for (int n = 0; n < 8; ++n) {
        int c = n * 8 + 2 * tc;
        float2 v0, v1;
        v0.x = oacc[n][0] * inv0; v0.y = oacc[n][1] * inv0;
        v1.x = oacc[n][2] * inv1; v1.y = oacc[n][3] * inv1;
        *(float2*)(Cg + (size_t)r0 * Dq + c)       = v0;
        *(float2*)(Cg + (size_t)(r0 + 8) * Dq + c) = v1;
    }
}

// ---------------- launch ----------------------------------------------------
extern "C" void kernel_launch(void* const* d_in, const int* in_sizes, int n_in,
                              void* d_out, int out_size)
{
    const float* x  = (const float*)d_in[0];
    const float* Wq = (const float*)d_in[1];
    const float* bq = (const float*)d_in[2];
    const float* Wk = (const float*)d_in[3];
    const float* bk = (const float*)d_in[4];
    const float* Wv = (const float*)d_in[5];
    const float* bv = (const float*)d_in[6];
    const float* Wo = (const float*)d_in[7];
    const float* bo = (const float*)d_in[8];
    float* out = (float*)d_out;

    float *pQ, *pK, *pV, *pC;
    cudaGetSymbolAddress((void**)&pQ, g_Q);
    cudaGetSymbolAddress((void**)&pK, g_K);
    cudaGetSymbolAddress((void**)&pV, g_V);
    cudaGetSymbolAddress((void**)&pC, g_C);

    const int SMEM_ATTN = (4 * 64 * APAD + 128 * APAD) * (int)sizeof(uint32_t);
    cudaFuncSetAttribute(attn_tc_kernel,
                         cudaFuncAttributeMaxDynamicSharedMemorySize, SMEM_ATTN);

    dim3 bGemm(256);

    // fused Q/K/V projections (tf32 tensor cores)
    dim3 gQKV(Dq / GBN, Mq / GBM, 3);
    tf32_qkv_kernel<<<gQKV, bGemm>>>(x, Wq, bq, Wk, bk, Wv, bv, pQ, pK, pV);

    // attention (tf32 tensor cores, split-compensated)
    dim3 gAttn(Tq / AQT, Hq, Bq);    // (16, 16, 2)
    attn_tc_kernel<<<gAttn, 256, SMEM_ATTN>>>(pQ, pK, pV, pC);

    // output projection (tf32 tensor cores)
    dim3 gGemm(Dq / GBN, Mq / GBM);
    tf32_gemm_kernel<<<gGemm, bGemm>>>(pC, Wo, bo, out, Mq, Dq, Dq);
}

// round 5
// speedup vs baseline: 2.6377x; 1.2529x over previous
#include <cuda_runtime.h>
#include <cuda_bf16.h>
#include <math.h>
#include <stdint.h>

// Problem constants
#define Bq 2
#define Tq 2048
#define Dq 1024
#define Hq 16
#define DKq 64
#define Mq (Bq*Tq)   // 4096

// ---------------- scratch (device globals; no allocation allowed) ----------
__device__ float g_Q[Mq * Dq];
__device__ float g_K[Mq * Dq];
__device__ float g_V[Mq * Dq];
__device__ float g_C[Mq * Dq];

// ---------------- tf32 helpers ----------------------------------------------
__device__ __forceinline__ uint32_t f2tf32(float f) {
    uint32_t r;
    asm volatile("cvt.rna.tf32.f32 %0, %1;" : "=r"(r) : "f"(f));
    return r;
}

__device__ __forceinline__ void mma_tf32(float c[4],
                                         uint32_t a0, uint32_t a1, uint32_t a2, uint32_t a3,
                                         uint32_t b0, uint32_t b1) {
    asm volatile(
        "mma.sync.aligned.m16n8k8.row.col.f32.tf32.tf32.f32 "
        "{%0,%1,%2,%3}, {%4,%5,%6,%7}, {%8,%9}, {%0,%1,%2,%3};"
        : "+f"(c[0]), "+f"(c[1]), "+f"(c[2]), "+f"(c[3])
        : "r"(a0), "r"(a1), "r"(a2), "r"(a3), "r"(b0), "r"(b1));
}

// ---------------- bf16 helpers ----------------------------------------------
// pack {lo: x, hi: y}
__device__ __forceinline__ uint32_t pack_bf16x2(float x, float y) {
    uint32_t r;
    asm("cvt.rn.bf16x2.f32 %0, %1, %2;" : "=r"(r) : "f"(y), "f"(x));
    return r;
}
__device__ __forceinline__ float bf_lo_f(uint32_t p) { return __uint_as_float(p << 16); }
__device__ __forceinline__ float bf_hi_f(uint32_t p) { return __uint_as_float(p & 0xffff0000u); }

__device__ __forceinline__ void mma_bf16(float c[4],
                                         uint32_t a0, uint32_t a1, uint32_t a2, uint32_t a3,
                                         uint32_t b0, uint32_t b1) {
    asm volatile(
        "mma.sync.aligned.m16n8k16.row.col.f32.bf16.bf16.f32 "
        "{%0,%1,%2,%3}, {%4,%5,%6,%7}, {%8,%9}, {%0,%1,%2,%3};"
        : "+f"(c[0]), "+f"(c[1]), "+f"(c[2]), "+f"(c[3])
        : "r"(a0), "r"(a1), "r"(a2), "r"(a3), "r"(b0), "r"(b1));
}

// ---------------- TF32 GEMM: Y = X @ W + bias --------------------------------
#define GBM 128
#define GBN 128
#define GBK 16
#define SMP 136

__device__ __forceinline__
void tf32_gemm_body(const float* __restrict__ X,
                    const float* __restrict__ W,
                    const float* __restrict__ bias,
                    float* __restrict__ Y,
                    int M, int N, int K,
                    int bm, int bn)
{
    __shared__ uint32_t As[GBK][SMP];
    __shared__ uint32_t Bs[GBK][SMP];

    const int tid  = threadIdx.x;
    const int wid  = tid >> 5;
    const int lane = tid & 31;
    const int gr   = lane >> 2;
    const int tc   = lane & 3;

    const int wm = wid & 1;
    const int wn = wid >> 1;

    const int a_r  = tid >> 1;
    const int a_kc = (tid & 1) * 8;
    const int b_r  = tid >> 4;
    const int b_c  = (tid & 15) * 4;

    const float* Xp = X + (size_t)(bm * GBM) * K;
    const float* Wp = W + (size_t)bn * GBN;

    float acc[4][4][4];
#pragma unroll
    for (int i = 0; i < 4; ++i)
#pragma unroll
        for (int j = 0; j < 4; ++j)
#pragma unroll
            for (int f = 0; f < 4; ++f) acc[i][j][f] = 0.f;

    for (int k0 = 0; k0 < K; k0 += GBK) {
        {
            float4 v0 = *(const float4*)(Xp + (size_t)a_r * K + k0 + a_kc);
            float4 v1 = *(const float4*)(Xp + (size_t)a_r * K + k0 + a_kc + 4);
            As[a_kc + 0][a_r] = f2tf32(v0.x);
            As[a_kc + 1][a_r] = f2tf32(v0.y);
            As[a_kc + 2][a_r] = f2tf32(v0.z);
            As[a_kc + 3][a_r] = f2tf32(v0.w);
            As[a_kc + 4][a_r] = f2tf32(v1.x);
            As[a_kc + 5][a_r] = f2tf32(v1.y);
            As[a_kc + 6][a_r] = f2tf32(v1.z);
            As[a_kc + 7][a_r] = f2tf32(v1.w);
        }
#pragma unroll
        for (int half = 0; half < 2; ++half) {
            int c = b_c + half * 64;
            float4 v = *(const float4*)(Wp + (size_t)(k0 + b_r) * N + c);
            uint4 u;
            u.x = f2tf32(v.x); u.y = f2tf32(v.y);
            u.z = f2tf32(v.z); u.w = f2tf32(v.w);
            *(uint4*)&Bs[b_r][c] = u;
        }
        __syncthreads();

#pragma unroll
        for (int ks = 0; ks < GBK; ks += 8) {
            uint32_t af[4][4];
            uint32_t bf[4][2];
#pragma unroll
            for (int mt = 0; mt < 4; ++mt) {
                int m0 = wm * 64 + mt * 16;
                af[mt][0] = As[ks + tc][m0 + gr];
                af[mt][1] = As[ks + tc][m0 + gr + 8];
                af[mt][2] = As[ks + tc + 4][m0 + gr];
                af[mt][3] = As[ks + tc + 4][m0 + gr + 8];
            }
#pragma unroll
            for (int nt = 0; nt < 4; ++nt) {
                int n0 = wn * 32 + nt * 8;
                bf[nt][0] = Bs[ks + tc][n0 + gr];
                bf[nt][1] = Bs[ks + tc + 4][n0 + gr];
            }
#pragma unroll
            for (int mt = 0; mt < 4; ++mt)
#pragma unroll
                for (int nt = 0; nt < 4; ++nt)
                    mma_tf32(acc[mt][nt],
                             af[mt][0], af[mt][1], af[mt][2], af[mt][3],
                             bf[nt][0], bf[nt][1]);
        }
        __syncthreads();
    }

#pragma unroll
    for (int mt = 0; mt < 4; ++mt) {
        int row = bm * GBM + wm * 64 + mt * 16 + gr;
#pragma unroll
        for (int nt = 0; nt < 4; ++nt) {
            int col = bn * GBN + wn * 32 + nt * 8 + 2 * tc;
            float b0 = bias[col], b1 = bias[col + 1];
            float2 lo, hi;
            lo.x = acc[mt][nt][0] + b0; lo.y = acc[mt][nt][1] + b1;
            hi.x = acc[mt][nt][2] + b0; hi.y = acc[mt][nt][3] + b1;
            *(float2*)(Y + (size_t)row * N + col)       = lo;
            *(float2*)(Y + (size_t)(row + 8) * N + col) = hi;
        }
    }
}

__global__ __launch_bounds__(256)
void tf32_gemm_kernel(const float* __restrict__ X,
                      const float* __restrict__ W,
                      const float* __restrict__ bias,
                      float* __restrict__ Y,
                      int M, int N, int K)
{
    tf32_gemm_body(X, W, bias, Y, M, N, K, blockIdx.y, blockIdx.x);
}

__global__ __launch_bounds__(256)
void tf32_qkv_kernel(const float* __restrict__ X,
                     const float* __restrict__ Wq, const float* __restrict__ bqv,
                     const float* __restrict__ Wk, const float* __restrict__ bkv,
                     const float* __restrict__ Wv, const float* __restrict__ bvv,
                     float* __restrict__ Qo, float* __restrict__ Ko, float* __restrict__ Vo)
{
    const float* W; const float* bias; float* Y;
    if (blockIdx.z == 0)      { W = Wq; bias = bqv; Y = Qo; }
    else if (blockIdx.z == 1) { W = Wk; bias = bkv; Y = Ko; }
    else                      { W = Wv; bias = bvv; Y = Vo; }
    tf32_gemm_body(X, W, bias, Y, Mq, Dq, Dq, blockIdx.y, blockIdx.x);
}

// ---------------- bf16-split tensor-core flash attention (causal) -----------
// Grid: (T/128, H, B). 256 threads = 8 warps; warp w owns Q rows [w*16, w*16+16).
// S = Qh*Kh + Ql*Kh + Qh*Kl (m16n8k16, ~16-bit mantissa); PV likewise with P split.
// P operand packs directly from accumulators (no smem round-trip).
#define AQT 128
#define AKT 64
#define KPADW 36    // uint32 row stride for pair-packed K/V (bank = 4*gr + tc)

__global__ __launch_bounds__(256, 2)
void attn_bf_kernel(const float* __restrict__ Q,
                    const float* __restrict__ K,
                    const float* __restrict__ V,
                    float* __restrict__ Ctx)
{
    __shared__ uint32_t Kh32[64 * KPADW];   // Kh32[key][dpair]
    __shared__ uint32_t Kl32[64 * KPADW];
    __shared__ uint32_t Vh32[64 * KPADW];   // Vh32[d][keypair]
    __shared__ uint32_t Vl32[64 * KPADW];

    const int b  = blockIdx.z;
    const int h  = blockIdx.y;
    const int qb = blockIdx.x;
    const int tid  = threadIdx.x;
    const int wid  = tid >> 5;
    const int lane = tid & 31;
    const int gr   = lane >> 2;   // 0..7
    const int tc   = lane & 3;    // 0..3

    const int qrow0 = qb * AQT;
    const float* Qg = Q + ((size_t)b * Tq + qrow0) * Dq + h * DKq;

    // register-resident Q fragments (hi/lo bf16 pairs), loaded direct from global
    // a-frag f: row = gr + (f&1)*8 ; cols = 2tc + (f>>1)*8 (+1)
    uint32_t qh[4][4], ql[4][4];
    {
        const int rbase = wid * 16;
#pragma unroll
        for (int kk = 0; kk < 4; ++kk) {
#pragma unroll
            for (int f = 0; f < 4; ++f) {
                int r = rbase + gr + (f & 1) * 8;
                int c = kk * 16 + 2 * tc + (f >> 1) * 8;
                float2 v = *(const float2*)(Qg + (size_t)r * Dq + c);
                v.x *= 0.125f; v.y *= 0.125f;
                uint32_t hpk = pack_bf16x2(v.x, v.y);
                qh[kk][f] = hpk;
                ql[kk][f] = pack_bf16x2(v.x - bf_lo_f(hpk), v.y - bf_hi_f(hpk));
            }
        }
    }

    float oacc[8][4];
#pragma unroll
    for (int n = 0; n < 8; ++n)
#pragma unroll
        for (int f = 0; f < 4; ++f) oacc[n][f] = 0.f;
    float m0 = -INFINITY, m1 = -INFINITY, l0 = 0.f, l1 = 0.f;

    const int row0g = qrow0 + wid * 16 + gr;
    const int row1g = row0g + 8;
    const int kbmax = (qb + 1) * 2;

    for (int kb = 0; kb < kbmax; ++kb) {
        const float* Kg = K + ((size_t)b * Tq + kb * AKT) * Dq + h * DKq;
        const float* Vg = V + ((size_t)b * Tq + kb * AKT) * Dq + h * DKq;

        // K: pair-packed along d. thread i -> key r=i>>5, dpair dp=i&31 (coalesced float2)
        for (int i = tid; i < 64 * 32; i += 256) {
            int r = i >> 5, dp = i & 31;
            float2 v = *(const float2*)(Kg + (size_t)r * Dq + 2 * dp);
            uint32_t hpk = pack_bf16x2(v.x, v.y);
            Kh32[r * KPADW + dp] = hpk;
            Kl32[r * KPADW + dp] = pack_bf16x2(v.x - bf_lo_f(hpk), v.y - bf_hi_f(hpk));
        }
        // V transposed: element (key r, d) -> Vh32[d][r/2] halves
        {
            __nv_bfloat16* Vhb = (__nv_bfloat16*)Vh32;
            __nv_bfloat16* Vlb = (__nv_bfloat16*)Vl32;
            for (int i = tid; i < 64 * 64; i += 256) {
                int r = i >> 6, d = i & 63;
                float v = Vg[(size_t)r * Dq + d];
                __nv_bfloat16 hb = __float2bfloat16(v);
                float lo = v - __bfloat162float(hb);
                Vhb[d * (2 * KPADW) + r] = hb;
                Vlb[d * (2 * KPADW) + r] = __float2bfloat16(lo);
            }
        }
        __syncthreads();

        const bool active = (kb * AKT <= qrow0 + wid * 16 + 15);

        if (active) {
            // ---- S = Q @ K^T : 3-term bf16 split, m16n8k16 ----
            float sacc[8][4];
#pragma unroll
            for (int n = 0; n < 8; ++n)
#pragma unroll
                for (int f = 0; f < 4; ++f) sacc[n][f] = 0.f;

#pragma unroll
            for (int kk = 0; kk < 4; ++kk) {
#pragma unroll
                for (int n = 0; n < 8; ++n) {
                    int base = (n * 8 + gr) * KPADW + kk * 8 + tc;
                    uint32_t bh0 = Kh32[base], bh1 = Kh32[base + 4];
                    uint32_t bl0 = Kl32[base], bl1 = Kl32[base + 4];
                    mma_bf16(sacc[n], qh[kk][0], qh[kk][1], qh[kk][2], qh[kk][3], bh0, bh1);
                    mma_bf16(sacc[n], ql[kk][0], ql[kk][1], ql[kk][2], ql[kk][3], bh0, bh1);
                    mma_bf16(sacc[n], qh[kk][0], qh[kk][1], qh[kk][2], qh[kk][3], bl0, bl1);
                }
            }

            // ---- causal mask ----
            if (kb * AKT + AKT - 1 > row0g) {
#pragma unroll
                for (int n = 0; n < 8; ++n) {
                    int colg = kb * AKT + n * 8 + 2 * tc;
                    if (colg     > row0g) sacc[n][0] = -INFINITY;
                    if (colg + 1 > row0g) sacc[n][1] = -INFINITY;
                    if (colg     > row1g) sacc[n][2] = -INFINITY;
                    if (colg + 1 > row1g) sacc[n][3] = -INFINITY;
                }
            }

            // ---- online softmax (rows warp-local, quad shfl reduce) ----
            float rmax0 = -INFINITY, rmax1 = -INFINITY;
#pragma unroll
            for (int n = 0; n < 8; ++n) {
                rmax0 = fmaxf(rmax0, fmaxf(sacc[n][0], sacc[n][1]));
                rmax1 = fmaxf(rmax1, fmaxf(sacc[n][2], sacc[n][3]));
            }
#pragma unroll
            for (int off = 1; off < 4; off <<= 1) {
                rmax0 = fmaxf(rmax0, __shfl_xor_sync(0xffffffffu, rmax0, off));
                rmax1 = fmaxf(rmax1, __shfl_xor_sync(0xffffffffu, rmax1, off));
            }

            float mn0 = fmaxf(m0, rmax0);
            float mn1 = fmaxf(m1, rmax1);
            float alpha0 = __expf(m0 - mn0);
            float alpha1 = __expf(m1 - mn1);

            float rsum0 = 0.f, rsum1 = 0.f;
#pragma unroll
            for (int n = 0; n < 8; ++n) {
                sacc[n][0] = __expf(sacc[n][0] - mn0);
                sacc[n][1] = __expf(sacc[n][1] - mn0);
                sacc[n][2] = __expf(sacc[n][2] - mn1);
                sacc[n][3] = __expf(sacc[n][3] - mn1);
                rsum0 += sacc[n][0] + sacc[n][1];
                rsum1 += sacc[n][2] + sacc[n][3];
            }
#pragma unroll
            for (int off = 1; off < 4; off <<= 1) {
                rsum0 += __shfl_xor_sync(0xffffffffu, rsum0, off);
                rsum1 += __shfl_xor_sync(0xffffffffu, rsum1, off);
            }

            m0 = mn0; m1 = mn1;
            l0 = l0 * alpha0 + rsum0;
            l1 = l1 * alpha1 + rsum1;
#pragma unroll
            for (int n = 0; n < 8; ++n) {
                oacc[n][0] *= alpha0; oacc[n][1] *= alpha0;
                oacc[n][2] *= alpha1; oacc[n][3] *= alpha1;
            }

            // ---- O += P @ V : pack P from accumulators, 3-term split ----
#pragma unroll
            for (int kkp = 0; kkp < 4; ++kkp) {
                // A-frag for keys [kkp*16, kkp*16+16): tiles 2kkp (lower 8) / 2kkp+1 (upper 8)
                float* pa = sacc[2 * kkp];
                float* pb = sacc[2 * kkp + 1];
                uint32_t ph0 = pack_bf16x2(pa[0], pa[1]);
                uint32_t ph1 = pack_bf16x2(pa[2], pa[3]);
                uint32_t ph2 = pack_bf16x2(pb[0], pb[1]);
                uint32_t ph3 = pack_bf16x2(pb[2], pb[3]);
                uint32_t pl0 = pack_bf16x2(pa[0] - bf_lo_f(ph0), pa[1] - bf_hi_f(ph0));
                uint32_t pl1 = pack_bf16x2(pa[2] - bf_lo_f(ph1), pa[3] - bf_hi_f(ph1));
                uint32_t pl2 = pack_bf16x2(pb[0] - bf_lo_f(ph2), pb[1] - bf_hi_f(ph2));
                uint32_t pl3 = pack_bf16x2(pb[2] - bf_lo_f(ph3), pb[3] - bf_hi_f(ph3));
#pragma unroll
                for (int n = 0; n < 8; ++n) {
                    int base = (n * 8 + gr) * KPADW + kkp * 8 + tc;
                    uint32_t bh0 = Vh32[base], bh1 = Vh32[base + 4];
                    uint32_t bl0 = Vl32[base], bl1 = Vl32[base + 4];
                    mma_bf16(oacc[n], ph0, ph1, ph2, ph3, bh0, bh1);
                    mma_bf16(oacc[n], pl0, pl1, pl2, pl3, bh0, bh1);
                    mma_bf16(oacc[n], ph0, ph1, ph2, ph3, bl0, bl1);
                }
            }
        }
        __syncthreads();   // protect K/V smem before next block's loads
    }

    // epilogue
    float inv0 = 1.f / l0;
    float inv1 = 1.f / l1;
    float* Cg = Ctx + ((size_t)b * Tq + qrow0) * Dq + h * DKq;
    const int r0 = wid * 16 + gr;
#pragma unroll
    for (int n = 0; n < 8; ++n) {
        int c = n * 8 + 2 * tc;
        float2 v0, v1;
        v0.x = oacc[n][0] * inv0; v0.y = oacc[n][1] * inv0;
        v1.x = oacc[n][2] * inv1; v1.y = oacc[n][3] * inv1;
        *(float2*)(Cg + (size_t)r0 * Dq + c)       = v0;
        *(float2*)(Cg + (size_t)(r0 + 8) * Dq + c) = v1;
    }
}

// ---------------- launch ----------------------------------------------------
extern "C" void kernel_launch(void* const* d_in, const int* in_sizes, int n_in,
                              void* d_out, int out_size)
{
    const float* x  = (const float*)d_in[0];
    const float* Wq = (const float*)d_in[1];
    const float* bq = (const float*)d_in[2];
    const float* Wk = (const float*)d_in[3];
    const float* bk = (const float*)d_in[4];
    const float* Wv = (const float*)d_in[5];
    const float* bv = (const float*)d_in[6];
    const float* Wo = (const float*)d_in[7];
    const float* bo = (const float*)d_in[8];
    float* out = (float*)d_out;

    float *pQ, *pK, *pV, *pC;
    cudaGetSymbolAddress((void**)&pQ, g_Q);
    cudaGetSymbolAddress((void**)&pK, g_K);
    cudaGetSymbolAddress((void**)&pV, g_V);
    cudaGetSymbolAddress((void**)&pC, g_C);

    dim3 bGemm(256);

    // fused Q/K/V projections (tf32 tensor cores)
    dim3 gQKV(Dq / GBN, Mq / GBM, 3);
    tf32_qkv_kernel<<<gQKV, bGemm>>>(x, Wq, bq, Wk, bk, Wv, bv, pQ, pK, pV);

    // attention (bf16 split-compensated tensor cores)
    dim3 gAttn(Tq / AQT, Hq, Bq);    // (16, 16, 2)
    attn_bf_kernel<<<gAttn, 256>>>(pQ, pK, pV, pC);

    // output projection (tf32 tensor cores)
    dim3 gGemm(Dq / GBN, Mq / GBM);
    tf32_gemm_kernel<<<gGemm, bGemm>>>(pC, Wo, bo, out, Mq, Dq, Dq);
}

// round 6
// speedup vs baseline: 2.6737x; 1.0137x over previous
#include <cuda_runtime.h>
#include <cuda_bf16.h>
#include <math.h>
#include <stdint.h>

// Problem constants
#define Bq 2
#define Tq 2048
#define Dq 1024
#define Hq 16
#define DKq 64
#define Mq (Bq*Tq)   // 4096

// ---------------- scratch (device globals; no allocation allowed) ----------
__device__ float g_Q[Mq * Dq];
__device__ float g_K[Mq * Dq];
__device__ float g_V[Mq * Dq];
__device__ float g_C[Mq * Dq];

// ---------------- tf32 helpers ----------------------------------------------
__device__ __forceinline__ uint32_t f2tf32(float f) {
    uint32_t r;
    asm volatile("cvt.rna.tf32.f32 %0, %1;" : "=r"(r) : "f"(f));
    return r;
}

__device__ __forceinline__ void mma_tf32(float c[4],
                                         uint32_t a0, uint32_t a1, uint32_t a2, uint32_t a3,
                                         uint32_t b0, uint32_t b1) {
    asm volatile(
        "mma.sync.aligned.m16n8k8.row.col.f32.tf32.tf32.f32 "
        "{%0,%1,%2,%3}, {%4,%5,%6,%7}, {%8,%9}, {%0,%1,%2,%3};"
        : "+f"(c[0]), "+f"(c[1]), "+f"(c[2]), "+f"(c[3])
        : "r"(a0), "r"(a1), "r"(a2), "r"(a3), "r"(b0), "r"(b1));
}

// ---------------- bf16 helpers ----------------------------------------------
__device__ __forceinline__ uint32_t pack_bf16x2(float x, float y) {
    uint32_t r;
    asm("cvt.rn.bf16x2.f32 %0, %1, %2;" : "=r"(r) : "f"(y), "f"(x));
    return r;
}
__device__ __forceinline__ float bf_lo_f(uint32_t p) { return __uint_as_float(p << 16); }
__device__ __forceinline__ float bf_hi_f(uint32_t p) { return __uint_as_float(p & 0xffff0000u); }

__device__ __forceinline__ void mma_bf16(float c[4],
                                         uint32_t a0, uint32_t a1, uint32_t a2, uint32_t a3,
                                         uint32_t b0, uint32_t b1) {
    asm volatile(
        "mma.sync.aligned.m16n8k16.row.col.f32.bf16.bf16.f32 "
        "{%0,%1,%2,%3}, {%4,%5,%6,%7}, {%8,%9}, {%0,%1,%2,%3};"
        : "+f"(c[0]), "+f"(c[1]), "+f"(c[2]), "+f"(c[3])
        : "r"(a0), "r"(a1), "r"(a2), "r"(a3), "r"(b0), "r"(b1));
}

// ---------------- Pipelined TF32 GEMM: Y = X @ W + bias ----------------------
// Double-buffered smem + register-prefetched LDG.
#define GBM 128
#define GBN 128
#define GBK 16
#define SMP 136

__device__ __forceinline__
void tf32_gemm_body(const float* __restrict__ X,
                    const float* __restrict__ W,
                    const float* __restrict__ bias,
                    float* __restrict__ Y,
                    int M, int N, int K,
                    int bm, int bn)
{
    __shared__ uint32_t As[2][GBK][SMP];
    __shared__ uint32_t Bs[2][GBK][SMP];

    const int tid  = threadIdx.x;
    const int wid  = tid >> 5;
    const int lane = tid & 31;
    const int gr   = lane >> 2;
    const int tc   = lane & 3;

    const int wm = wid & 1;
    const int wn = wid >> 1;

    const int a_r  = tid >> 1;
    const int a_kc = (tid & 1) * 8;
    const int b_r  = tid >> 4;
    const int b_c  = (tid & 15) * 4;

    const float* Xp = X + (size_t)(bm * GBM) * K;
    const float* Wp = W + (size_t)bn * GBN;

    float acc[4][4][4];
#pragma unroll
    for (int i = 0; i < 4; ++i)
#pragma unroll
        for (int j = 0; j < 4; ++j)
#pragma unroll
            for (int f = 0; f < 4; ++f) acc[i][j][f] = 0.f;

    float4 la0, la1, lb0, lb1;   // LDG prefetch buffer

    // prologue: load tile 0
    la0 = *(const float4*)(Xp + (size_t)a_r * K + a_kc);
    la1 = *(const float4*)(Xp + (size_t)a_r * K + a_kc + 4);
    lb0 = *(const float4*)(Wp + (size_t)b_r * N + b_c);
    lb1 = *(const float4*)(Wp + (size_t)b_r * N + b_c + 64);

    // store tile 0 into stage 0
    {
        As[0][a_kc + 0][a_r] = f2tf32(la0.x);
        As[0][a_kc + 1][a_r] = f2tf32(la0.y);
        As[0][a_kc + 2][a_r] = f2tf32(la0.z);
        As[0][a_kc + 3][a_r] = f2tf32(la0.w);
        As[0][a_kc + 4][a_r] = f2tf32(la1.x);
        As[0][a_kc + 5][a_r] = f2tf32(la1.y);
        As[0][a_kc + 6][a_r] = f2tf32(la1.z);
        As[0][a_kc + 7][a_r] = f2tf32(la1.w);
        uint4 u0, u1;
        u0.x = f2tf32(lb0.x); u0.y = f2tf32(lb0.y);
        u0.z = f2tf32(lb0.z); u0.w = f2tf32(lb0.w);
        u1.x = f2tf32(lb1.x); u1.y = f2tf32(lb1.y);
        u1.z = f2tf32(lb1.z); u1.w = f2tf32(lb1.w);
        *(uint4*)&Bs[0][b_r][b_c]      = u0;
        *(uint4*)&Bs[0][b_r][b_c + 64] = u1;
    }
    __syncthreads();

    int cur = 0;
    for (int k0 = 0; k0 < K; k0 += GBK) {
        const bool has_next = (k0 + GBK < K);
        if (has_next) {
            // prefetch next tile into registers; latency hidden by compute below
            la0 = *(const float4*)(Xp + (size_t)a_r * K + k0 + GBK + a_kc);
            la1 = *(const float4*)(Xp + (size_t)a_r * K + k0 + GBK + a_kc + 4);
            lb0 = *(const float4*)(Wp + (size_t)(k0 + GBK + b_r) * N + b_c);
            lb1 = *(const float4*)(Wp + (size_t)(k0 + GBK + b_r) * N + b_c + 64);
        }

#pragma unroll
        for (int ks = 0; ks < GBK; ks += 8) {
            uint32_t af[4][4];
            uint32_t bf[4][2];
#pragma unroll
            for (int mt = 0; mt < 4; ++mt) {
                int m0 = wm * 64 + mt * 16;
                af[mt][0] = As[cur][ks + tc][m0 + gr];
                af[mt][1] = As[cur][ks + tc][m0 + gr + 8];
                af[mt][2] = As[cur][ks + tc + 4][m0 + gr];
                af[mt][3] = As[cur][ks + tc + 4][m0 + gr + 8];
            }
#pragma unroll
            for (int nt = 0; nt < 4; ++nt) {
                int n0 = wn * 32 + nt * 8;
                bf[nt][0] = Bs[cur][ks + tc][n0 + gr];
                bf[nt][1] = Bs[cur][ks + tc + 4][n0 + gr];
            }
#pragma unroll
            for (int mt = 0; mt < 4; ++mt)
#pragma unroll
                for (int nt = 0; nt < 4; ++nt)
                    mma_tf32(acc[mt][nt],
                             af[mt][0], af[mt][1], af[mt][2], af[mt][3],
                             bf[nt][0], bf[nt][1]);
        }

        if (has_next) {
            const int nxt = cur ^ 1;
            As[nxt][a_kc + 0][a_r] = f2tf32(la0.x);
            As[nxt][a_kc + 1][a_r] = f2tf32(la0.y);
            As[nxt][a_kc + 2][a_r] = f2tf32(la0.z);
            As[nxt][a_kc + 3][a_r] = f2tf32(la0.w);
            As[nxt][a_kc + 4][a_r] = f2tf32(la1.x);
            As[nxt][a_kc + 5][a_r] = f2tf32(la1.y);
            As[nxt][a_kc + 6][a_r] = f2tf32(la1.z);
            As[nxt][a_kc + 7][a_r] = f2tf32(la1.w);
            uint4 u0, u1;
            u0.x = f2tf32(lb0.x); u0.y = f2tf32(lb0.y);
            u0.z = f2tf32(lb0.z); u0.w = f2tf32(lb0.w);
            u1.x = f2tf32(lb1.x); u1.y = f2tf32(lb1.y);
            u1.z = f2tf32(lb1.z); u1.w = f2tf32(lb1.w);
            *(uint4*)&Bs[nxt][b_r][b_c]      = u0;
            *(uint4*)&Bs[nxt][b_r][b_c + 64] = u1;
            __syncthreads();
            cur = nxt;
        }
    }

#pragma unroll
    for (int mt = 0; mt < 4; ++mt) {
        int row = bm * GBM + wm * 64 + mt * 16 + gr;
#pragma unroll
        for (int nt = 0; nt < 4; ++nt) {
            int col = bn * GBN + wn * 32 + nt * 8 + 2 * tc;
            float b0 = bias[col], b1 = bias[col + 1];
            float2 lo, hi;
            lo.x = acc[mt][nt][0] + b0; lo.y = acc[mt][nt][1] + b1;
            hi.x = acc[mt][nt][2] + b0; hi.y = acc[mt][nt][3] + b1;
            *(float2*)(Y + (size_t)row * N + col)       = lo;
            *(float2*)(Y + (size_t)(row + 8) * N + col) = hi;
        }
    }
}

__global__ __launch_bounds__(256, 2)
void tf32_gemm_kernel(const float* __restrict__ X,
                      const float* __restrict__ W,
                      const float* __restrict__ bias,
                      float* __restrict__ Y,
                      int M, int N, int K)
{
    tf32_gemm_body(X, W, bias, Y, M, N, K, blockIdx.y, blockIdx.x);
}

__global__ __launch_bounds__(256, 2)
void tf32_qkv_kernel(const float* __restrict__ X,
                     const float* __restrict__ Wq, const float* __restrict__ bqv,
                     const float* __restrict__ Wk, const float* __restrict__ bkv,
                     const float* __restrict__ Wv, const float* __restrict__ bvv,
                     float* __restrict__ Qo, float* __restrict__ Ko, float* __restrict__ Vo)
{
    const float* W; const float* bias; float* Y;
    if (blockIdx.z == 0)      { W = Wq; bias = bqv; Y = Qo; }
    else if (blockIdx.z == 1) { W = Wk; bias = bkv; Y = Ko; }
    else                      { W = Wv; bias = bvv; Y = Vo; }
    tf32_gemm_body(X, W, bias, Y, Mq, Dq, Dq, blockIdx.y, blockIdx.x);
}

// ---------------- bf16-split tensor-core flash attention (causal) -----------
#define AQT 128
#define AKT 64
#define KPADW 36

__global__ __launch_bounds__(256, 2)
void attn_bf_kernel(const float* __restrict__ Q,
                    const float* __restrict__ K,
                    const float* __restrict__ V,
                    float* __restrict__ Ctx)
{
    __shared__ uint32_t Kh32[64 * KPADW];
    __shared__ uint32_t Kl32[64 * KPADW];
    __shared__ uint32_t Vh32[64 * KPADW];
    __shared__ uint32_t Vl32[64 * KPADW];

    const int b  = blockIdx.z;
    const int h  = blockIdx.y;
    // heavy causal blocks first: better tail packing across SMs
    const int qb = gridDim.x - 1 - blockIdx.x;
    const int tid  = threadIdx.x;
    const int wid  = tid >> 5;
    const int lane = tid & 31;
    const int gr   = lane >> 2;
    const int tc   = lane & 3;

    const int qrow0 = qb * AQT;
    const float* Qg = Q + ((size_t)b * Tq + qrow0) * Dq + h * DKq;

    uint32_t qh[4][4], ql[4][4];
    {
        const int rbase = wid * 16;
#pragma unroll
        for (int kk = 0; kk < 4; ++kk) {
#pragma unroll
            for (int f = 0; f < 4; ++f) {
                int r = rbase + gr + (f & 1) * 8;
                int c = kk * 16 + 2 * tc + (f >> 1) * 8;
                float2 v = *(const float2*)(Qg + (size_t)r * Dq + c);
                v.x *= 0.125f; v.y *= 0.125f;
                uint32_t hpk = pack_bf16x2(v.x, v.y);
                qh[kk][f] = hpk;
                ql[kk][f] = pack_bf16x2(v.x - bf_lo_f(hpk), v.y - bf_hi_f(hpk));
            }
        }
    }

    float oacc[8][4];
#pragma unroll
    for (int n = 0; n < 8; ++n)
#pragma unroll
        for (int f = 0; f < 4; ++f) oacc[n][f] = 0.f;
    float m0 = -INFINITY, m1 = -INFINITY, l0 = 0.f, l1 = 0.f;

    const int row0g = qrow0 + wid * 16 + gr;
    const int row1g = row0g + 8;
    const int kbmax = (qb + 1) * 2;

    for (int kb = 0; kb < kbmax; ++kb) {
        const float* Kg = K + ((size_t)b * Tq + kb * AKT) * Dq + h * DKq;
        const float* Vg = V + ((size_t)b * Tq + kb * AKT) * Dq + h * DKq;

        for (int i = tid; i < 64 * 32; i += 256) {
            int r = i >> 5, dp = i & 31;
            float2 v = *(const float2*)(Kg + (size_t)r * Dq + 2 * dp);
            uint32_t hpk = pack_bf16x2(v.x, v.y);
            Kh32[r * KPADW + dp] = hpk;
            Kl32[r * KPADW + dp] = pack_bf16x2(v.x - bf_lo_f(hpk), v.y - bf_hi_f(hpk));
        }
        {
            __nv_bfloat16* Vhb = (__nv_bfloat16*)Vh32;
            __nv_bfloat16* Vlb = (__nv_bfloat16*)Vl32;
            for (int i = tid; i < 64 * 64; i += 256) {
                int r = i >> 6, d = i & 63;
                float v = Vg[(size_t)r * Dq + d];
                __nv_bfloat16 hb = __float2bfloat16(v);
                float lo = v - __bfloat162float(hb);
                Vhb[d * (2 * KPADW) + r] = hb;
                Vlb[d * (2 * KPADW) + r] = __float2bfloat16(lo);
            }
        }
        __syncthreads();

        const bool active = (kb * AKT <= qrow0 + wid * 16 + 15);

        if (active) {
            float sacc[8][4];
#pragma unroll
            for (int n = 0; n < 8; ++n)
#pragma unroll
                for (int f = 0; f < 4; ++f) sacc[n][f] = 0.f;

#pragma unroll
            for (int kk = 0; kk < 4; ++kk) {
#pragma unroll
                for (int n = 0; n < 8; ++n) {
                    int base = (n * 8 + gr) * KPADW + kk * 8 + tc;
                    uint32_t bh0 = Kh32[base], bh1 = Kh32[base + 4];
                    uint32_t bl0 = Kl32[base], bl1 = Kl32[base + 4];
                    mma_bf16(sacc[n], qh[kk][0], qh[kk][1], qh[kk][2], qh[kk][3], bh0, bh1);
                    mma_bf16(sacc[n], ql[kk][0], ql[kk][1], ql[kk][2], ql[kk][3], bh0, bh1);
                    mma_bf16(sacc[n], qh[kk][0], qh[kk][1], qh[kk][2], qh[kk][3], bl0, bl1);
                }
            }

            if (kb * AKT + AKT - 1 > row0g) {
#pragma unroll
                for (int n = 0; n < 8; ++n) {
                    int colg = kb * AKT + n * 8 + 2 * tc;
                    if (colg     > row0g) sacc[n][0] = -INFINITY;
                    if (colg + 1 > row0g) sacc[n][1] = -INFINITY;
                    if (colg     > row1g) sacc[n][2] = -INFINITY;
                    if (colg + 1 > row1g) sacc[n][3] = -INFINITY;
                }
            }

            float rmax0 = -INFINITY, rmax1 = -INFINITY;
#pragma unroll
            for (int n = 0; n < 8; ++n) {
                rmax0 = fmaxf(rmax0, fmaxf(sacc[n][0], sacc[n][1]));
                rmax1 = fmaxf(rmax1, fmaxf(sacc[n][2], sacc[n][3]));
            }
#pragma unroll
            for (int off = 1; off < 4; off <<= 1) {
                rmax0 = fmaxf(rmax0, __shfl_xor_sync(0xffffffffu, rmax0, off));
                rmax1 = fmaxf(rmax1, __shfl_xor_sync(0xffffffffu, rmax1, off));
            }

            float mn0 = fmaxf(m0, rmax0);
            float mn1 = fmaxf(m1, rmax1);
            float alpha0 = __expf(m0 - mn0);
            float alpha1 = __expf(m1 - mn1);

            float rsum0 = 0.f, rsum1 = 0.f;
#pragma unroll
            for (int n = 0; n < 8; ++n) {
                sacc[n][0] = __expf(sacc[n][0] - mn0);
                sacc[n][1] = __expf(sacc[n][1] - mn0);
                sacc[n][2] = __expf(sacc[n][2] - mn1);
                sacc[n][3] = __expf(sacc[n][3] - mn1);
                rsum0 += sacc[n][0] + sacc[n][1];
                rsum1 += sacc[n][2] + sacc[n][3];
            }
#pragma unroll
            for (int off = 1; off < 4; off <<= 1) {
                rsum0 += __shfl_xor_sync(0xffffffffu, rsum0, off);
                rsum1 += __shfl_xor_sync(0xffffffffu, rsum1, off);
            }

            m0 = mn0; m1 = mn1;
            l0 = l0 * alpha0 + rsum0;
            l1 = l1 * alpha1 + rsum1;
#pragma unroll
            for (int n = 0; n < 8; ++n) {
                oacc[n][0] *= alpha0; oacc[n][1] *= alpha0;
                oacc[n][2] *= alpha1; oacc[n][3] *= alpha1;
            }

#pragma unroll
            for (int kkp = 0; kkp < 4; ++kkp) {
                float* pa = sacc[2 * kkp];
                float* pb = sacc[2 * kkp + 1];
                uint32_t ph0 = pack_bf16x2(pa[0], pa[1]);
                uint32_t ph1 = pack_bf16x2(pa[2], pa[3]);
                uint32_t ph2 = pack_bf16x2(pb[0], pb[1]);
                uint32_t ph3 = pack_bf16x2(pb[2], pb[3]);
                uint32_t pl0 = pack_bf16x2(pa[0] - bf_lo_f(ph0), pa[1] - bf_hi_f(ph0));
                uint32_t pl1 = pack_bf16x2(pa[2] - bf_lo_f(ph1), pa[3] - bf_hi_f(ph1));
                uint32_t pl2 = pack_bf16x2(pb[0] - bf_lo_f(ph2), pb[1] - bf_hi_f(ph2));
                uint32_t pl3 = pack_bf16x2(pb[2] - bf_lo_f(ph3), pb[3] - bf_hi_f(ph3));
#pragma unroll
                for (int n = 0; n < 8; ++n) {
                    int base = (n * 8 + gr) * KPADW + kkp * 8 + tc;
                    uint32_t bh0 = Vh32[base], bh1 = Vh32[base + 4];
                    uint32_t bl0 = Vl32[base], bl1 = Vl32[base + 4];
                    mma_bf16(oacc[n], ph0, ph1, ph2, ph3, bh0, bh1);
                    mma_bf16(oacc[n], pl0, pl1, pl2, pl3, bh0, bh1);
                    mma_bf16(oacc[n], ph0, ph1, ph2, ph3, bl0, bl1);
                }
            }
        }
        __syncthreads();
    }

    float inv0 = 1.f / l0;
    float inv1 = 1.f / l1;
    float* Cg = Ctx + ((size_t)b * Tq + qrow0) * Dq + h * DKq;
    const int r0 = wid * 16 + gr;
#pragma unroll
    for (int n = 0; n < 8; ++n) {
        int c = n * 8 + 2 * tc;
        float2 v0, v1;
        v0.x = oacc[n][0] * inv0; v0.y = oacc[n][1] * inv0;
        v1.x = oacc[n][2] * inv1; v1.y = oacc[n][3] * inv1;
        *(float2*)(Cg + (size_t)r0 * Dq + c)       = v0;
        *(float2*)(Cg + (size_t)(r0 + 8) * Dq + c) = v1;
    }
}

// ---------------- launch ----------------------------------------------------
extern "C" void kernel_launch(void* const* d_in, const int* in_sizes, int n_in,
                              void* d_out, int out_size)
{
    const float* x  = (const float*)d_in[0];
    const float* Wq = (const float*)d_in[1];
    const float* bq = (const float*)d_in[2];
    const float* Wk = (const float*)d_in[3];
    const float* bk = (const float*)d_in[4];
    const float* Wv = (const float*)d_in[5];
    const float* bv = (const float*)d_in[6];
    const float* Wo = (const float*)d_in[7];
    const float* bo = (const float*)d_in[8];
    float* out = (float*)d_out;

    float *pQ, *pK, *pV, *pC;
    cudaGetSymbolAddress((void**)&pQ, g_Q);
    cudaGetSymbolAddress((void**)&pK, g_K);
    cudaGetSymbolAddress((void**)&pV, g_V);
    cudaGetSymbolAddress((void**)&pC, g_C);

    dim3 bGemm(256);

    // fused Q/K/V projections (pipelined tf32 tensor cores)
    dim3 gQKV(Dq / GBN, Mq / GBM, 3);
    tf32_qkv_kernel<<<gQKV, bGemm>>>(x, Wq, bq, Wk, bk, Wv, bv, pQ, pK, pV);

    // attention (bf16 split-compensated tensor cores)
    dim3 gAttn(Tq / AQT, Hq, Bq);    // (16, 16, 2)
    attn_bf_kernel<<<gAttn, 256>>>(pQ, pK, pV, pC);

    // output projection (pipelined tf32 tensor cores)
    dim3 gGemm(Dq / GBN, Mq / GBM);
    tf32_gemm_kernel<<<gGemm, bGemm>>>(pC, Wo, bo, out, Mq, Dq, Dq);
}